// round 12
// baseline (speedup 1.0000x reference)
#include <cuda_runtime.h>
#include <cuda_fp16.h>
#include <cstdint>

// Problem shape (fixed for this registry entry)
#define B_  8
#define N_  2048
#define C_  64
#define H_  4
#define D_  64
#define HD_ 256          // H*D
#define NW_ (N_/32)      // mask words per row = 64
#define LOG2E 1.4426950408889634f

// ---------------- scratch (device globals: no allocation allowed) -----------
__device__ __half  g_hH [B_*H_*N_*D_];    // layer1 features, f16 hi
__device__ __half  g_hL [B_*H_*N_*D_];    // layer1 features, f16 lo (residual)
__device__ __half  g_h2H[B_*N_*D_];       // layer2 features hi
__device__ __half  g_h2L[B_*N_*D_];       // layer2 features lo
__device__ float    g_z  [B_*N_*HD_];     // concat+lrelu of layer-1 output
__device__ unsigned g_maskT[NW_*N_];      // transposed bitmask [w][n]

__device__ __forceinline__ float ex2(float x) {
    float y;
    asm("ex2.approx.f32 %0, %1;" : "=f"(y) : "f"(x));
    return y;
}
__device__ __forceinline__ uint32_t smem_u32(const void* p) {
    uint32_t a;
    asm("{ .reg .u64 t; cvta.to.shared.u64 t, %1; cvt.u32.u64 %0, t; }" : "=r"(a) : "l"(p));
    return a;
}
__device__ __forceinline__ void cp16(uint32_t saddr, const void* g) {
    asm volatile("cp.async.ca.shared.global [%0], [%1], 16;"
                 :: "r"(saddr), "l"(__cvta_generic_to_global(g)));
}
__device__ __forceinline__ void ldsm4(uint32_t r[4], uint32_t addr) {
    asm volatile("ldmatrix.sync.aligned.m8n8.x4.shared.b16 {%0,%1,%2,%3}, [%4];"
                 : "=r"(r[0]), "=r"(r[1]), "=r"(r[2]), "=r"(r[3]) : "r"(addr));
}
__device__ __forceinline__ void ldsm4t(uint32_t r[4], uint32_t addr) {
    asm volatile("ldmatrix.sync.aligned.m8n8.x4.trans.shared.b16 {%0,%1,%2,%3}, [%4];"
                 : "=r"(r[0]), "=r"(r[1]), "=r"(r[2]), "=r"(r[3]) : "r"(addr));
}
__device__ __forceinline__ void mma16816(float d[4], const uint32_t a[4], const uint32_t b[2]) {
    asm volatile("mma.sync.aligned.m16n8k16.row.col.f32.f16.f16.f32 "
                 "{%0,%1,%2,%3}, {%4,%5,%6,%7}, {%8,%9}, {%0,%1,%2,%3};"
                 : "+f"(d[0]), "+f"(d[1]), "+f"(d[2]), "+f"(d[3])
                 : "r"(a[0]), "r"(a[1]), "r"(a[2]), "r"(a[3]), "r"(b[0]), "r"(b[1]));
}
// f16-accumulate variant (for the small Ql*Kh correction term)
__device__ __forceinline__ void mma16816h(uint32_t d[2], const uint32_t a[4], const uint32_t b[2]) {
    asm volatile("mma.sync.aligned.m16n8k16.row.col.f16.f16.f16.f16 "
                 "{%0,%1}, {%2,%3,%4,%5}, {%6,%7}, {%0,%1};"
                 : "+r"(d[0]), "+r"(d[1])
                 : "r"(a[0]), "r"(a[1]), "r"(a[2]), "r"(a[3]), "r"(b[0]), "r"(b[1]));
}
__device__ __forceinline__ float lrelu(float a) { return a > 0.f ? a : 0.2f * a; }

__device__ __forceinline__ void split_store(__half* dH, __half* dL, size_t idx,
                                            float v0, float v1) {
    __half h0 = __float2half_rn(v0), h1 = __float2half_rn(v1);
    __half l0 = __float2half_rn(v0 - __half2float(h0));
    __half l1 = __float2half_rn(v1 - __half2float(h1));
    *(__half2*)&dH[idx] = __halves2half2(h0, h1);
    *(__half2*)&dL[idx] = __halves2half2(l0, l1);
}

// ---------------- mask build ------------------------------------------------
__global__ void build_mask_kernel(const int* __restrict__ graph) {
    int gwarp = (blockIdx.x * blockDim.x + threadIdx.x) >> 5;
    int lane  = threadIdx.x & 31;
    if (gwarp >= N_ * NW_) return;
    int n = gwarp >> 6;
    int w = gwarp & (NW_ - 1);
    int m = w * 32 + lane;
    bool bit = (graph[(size_t)n * N_ + m] != 0) || (m == n);
    unsigned word = __ballot_sync(0xffffffffu, bit);
    if (lane == 0) g_maskT[w * N_ + n] = word;
}

// ---------------- proj1: one head per blockIdx.y (grid 256 x 4) -------------
__global__ void proj1_kernel(const float* __restrict__ x,
                             const float* __restrict__ Wh) {
    __shared__ float xs[64][65];
    __shared__ float ws[64][65];
    int t    = threadIdx.x;              // 256 threads
    int row0 = blockIdx.x * 64;          // flattened b*N + n
    int h    = blockIdx.y;
    for (int i = t; i < 64 * 64; i += 256) {
        int r = i >> 6, c = i & 63;
        xs[r][c] = x[(size_t)(row0 + r) * C_ + c];
        ws[r][c] = Wh[((size_t)h * D_ + r) * C_ + c];
    }
    __syncthreads();
    int d0 = (t & 15) * 4;
    int r0 = (t >> 4) * 4;
    int b     = row0 >> 11;
    int nbase = row0 & (N_ - 1);
    float acc[4][4] = {};
    #pragma unroll 8
    for (int c = 0; c < 64; ++c) {
        float xv[4], wv[4];
        #pragma unroll
        for (int i = 0; i < 4; ++i) { xv[i] = xs[r0 + i][c]; wv[i] = ws[d0 + i][c]; }
        #pragma unroll
        for (int i = 0; i < 4; ++i)
            #pragma unroll
            for (int j = 0; j < 4; ++j)
                acc[i][j] += xv[i] * wv[j];
    }
    #pragma unroll
    for (int i = 0; i < 4; ++i) {
        size_t base = (((size_t)(b * H_ + h) * N_) + nbase + r0 + i) * D_ + d0;
        split_store(g_hH, g_hL, base,     acc[i][0], acc[i][1]);
        split_store(g_hH, g_hL, base + 2, acc[i][2], acc[i][3]);
    }
}

// ---------------- proj2: 32 rows/block (512 blocks, grid-limit fix) ---------
__global__ void proj2_kernel(const float* __restrict__ Wo) {
    __shared__ float zs[32][65];
    __shared__ float ws[64][65];
    int t    = threadIdx.x;              // 256 threads
    int row0 = blockIdx.x * 32;
    int d0 = (t & 15) * 4;
    int r0 = (t >> 4) * 2;               // 0..30
    float acc[2][4] = {};
    for (int kc = 0; kc < 4; ++kc) {
        __syncthreads();
        for (int i = t; i < 32 * 64; i += 256) {
            int r = i >> 6, c = i & 63;
            zs[r][c] = g_z[(size_t)(row0 + r) * HD_ + kc * 64 + c];
        }
        for (int i = t; i < 64 * 64; i += 256) {
            int r = i >> 6, c = i & 63;
            ws[r][c] = Wo[(size_t)r * HD_ + kc * 64 + c];
        }
        __syncthreads();
        #pragma unroll 8
        for (int c = 0; c < 64; ++c) {
            float x0 = zs[r0][c], x1 = zs[r0 + 1][c];
            float wv[4];
            #pragma unroll
            for (int j = 0; j < 4; ++j) wv[j] = ws[d0 + j][c];
            #pragma unroll
            for (int j = 0; j < 4; ++j) {
                acc[0][j] += x0 * wv[j];
                acc[1][j] += x1 * wv[j];
            }
        }
    }
    #pragma unroll
    for (int i = 0; i < 2; ++i) {
        size_t base = (size_t)(row0 + r0 + i) * D_ + d0;
        split_store(g_h2H, g_h2L, base,     acc[i][0], acc[i][1]);
        split_store(g_h2H, g_h2L, base + 2, acc[i][2], acc[i][3]);
    }
}

// ================= HMMA flash attention, 4 warps / 64 rows ===================
// KV tile = 64 cols, 3-deep cp.async ring (KH only), 3 blocks/SM.
// S = Qh*Kh (f32-acc) + Ql*Kh (f16-acc correction, magnitude ~1e-3),
// P f16, O = P*Vh (f32-acc).
#define SQ 72                          // smem row stride in halves
#define NT 32                          // KV tiles
#define SM_QH 0
#define SM_QL 4608
#define SM_K  9216                     // ring starts after QH/QL
#define KBUF_HALVES 4608               // KH[64][72]
#define SMEM_ATT ((9216 + 3 * KBUF_HALVES) * 2)   // 46080 bytes

template <int LAYER>
__global__ void __launch_bounds__(128, 3)
attn_mma(const float* __restrict__ bias,
         const float* __restrict__ gamma,
         const float* __restrict__ beta,
         float* __restrict__ outp) {
    extern __shared__ __half smh[];
    const int t    = threadIdx.x;
    const int wid  = t >> 5;            // 0..3
    const int lane = t & 31;
    const int g    = lane >> 2;
    const int tg   = lane & 3;
    const int wr0  = wid << 4;
    const int bh   = blockIdx.x;
    const int row0 = blockIdx.y << 6;   // 64 query rows per block
    const __half* hH = (LAYER == 1 ? g_hH : g_h2H) + (size_t)bh * (N_ * D_);
    const __half* hL = (LAYER == 1 ? g_hL : g_h2L) + (size_t)bh * (N_ * D_);
    const uint32_t sbase = smem_u32(smh);

    // ---- stage Q hi + lo (64 rows) via plain loads ----
    {
        const uint4* sH = (const uint4*)(hH + (size_t)row0 * D_);
        const uint4* sL = (const uint4*)(hL + (size_t)row0 * D_);
        #pragma unroll
        for (int i = 0; i < 4; ++i) {
            int idx = t + (i << 7);            // 0..511
            int r = idx >> 3, c8 = (idx & 7) << 3;
            *(uint4*)&smh[SM_QH + r * SQ + c8] = sH[idx];
            *(uint4*)&smh[SM_QL + r * SQ + c8] = sL[idx];
        }
    }
    // ---- prefetch K tiles 0,1 (hi only) into ring buffers 0,1 ----
    #pragma unroll
    for (int pt = 0; pt < 2; ++pt) {
        const uint4* sH = (const uint4*)(hH + (size_t)pt * (64 * D_));
        uint32_t kb = sbase + (uint32_t)(SM_K + pt * KBUF_HALVES) * 2;
        #pragma unroll
        for (int i = 0; i < 4; ++i) {
            int idx = t + (i << 7);            // 0..511
            int r = idx >> 3, c8 = (idx & 7) << 3;
            cp16(kb + (((uint32_t)(r * SQ + c8)) << 1), sH + idx);
        }
        asm volatile("cp.async.commit_group;" ::: "memory");
    }
    __syncthreads();

    // ---- preload Q A-frags (hi and lo) ----
    uint32_t qh[4][4], ql[4][4];
    {
        int arow  = wr0 + (lane & 15);
        int acolb = (lane >> 4) << 3;
        #pragma unroll
        for (int kf = 0; kf < 4; ++kf) {
            ldsm4(qh[kf], sbase + ((uint32_t)(SM_QH + arow * SQ + (kf << 4) + acolb) << 1));
            ldsm4(ql[kf], sbase + ((uint32_t)(SM_QL + arow * SQ + (kf << 4) + acolb) << 1));
        }
    }

    float oacc[8][4];
    #pragma unroll
    for (int i = 0; i < 8; ++i)
        #pragma unroll
        for (int j = 0; j < 4; ++j) oacc[i][j] = 0.f;
    float rs0 = 0.f, rs1 = 0.f, mr0 = -1e30f, mr1 = -1e30f;
    const int grow0 = row0 + wr0 + g;

    int buf = 0;
    #pragma unroll 1
    for (int tile = 0; tile < NT; ++tile) {
        asm volatile("cp.async.wait_group 1;" ::: "memory");
        __syncthreads();
        // ---- prefetch tile+2 into ring slot ----
        {
            int pt = tile + 2;
            if (pt < NT) {
                int pb = buf + 2; if (pb >= 3) pb -= 3;
                const uint4* sH = (const uint4*)(hH + (size_t)pt * (64 * D_));
                uint32_t kb = sbase + (uint32_t)(SM_K + pb * KBUF_HALVES) * 2;
                #pragma unroll
                for (int i = 0; i < 4; ++i) {
                    int idx = t + (i << 7);
                    int r = idx >> 3, c8 = (idx & 7) << 3;
                    cp16(kb + (((uint32_t)(r * SQ + c8)) << 1), sH + idx);
                }
            }
            asm volatile("cp.async.commit_group;" ::: "memory");   // empty group ok
        }
        unsigned mw0[2], mw1[2];
        #pragma unroll
        for (int w = 0; w < 2; ++w) {
            mw0[w] = g_maskT[(size_t)((tile << 1) + w) * N_ + grow0];
            mw1[w] = g_maskT[(size_t)((tile << 1) + w) * N_ + grow0 + 8];
        }

        const uint32_t kbH = sbase + (uint32_t)(SM_K + buf * KBUF_HALVES) * 2;

        // ---- GEMM-S: Qh*Kh in f32-acc, Ql*Kh correction in f16-acc ----
        float sacc[8][4];
        uint32_t cacc[8][2];
        #pragma unroll
        for (int i = 0; i < 8; ++i) {
            #pragma unroll
            for (int j = 0; j < 4; ++j) sacc[i][j] = 0.f;
            cacc[i][0] = 0u; cacc[i][1] = 0u;
        }
        {
            const int brow = ((lane >> 4) << 3) + (lane & 7);
            const int bcol = ((lane >> 3) & 1) << 3;
            #pragma unroll
            for (int kf = 0; kf < 4; ++kf) {
                uint32_t bfr[8][2];
                #pragma unroll
                for (int j = 0; j < 4; ++j) {
                    uint32_t r4[4];
                    ldsm4(r4, kbH + ((uint32_t)(((j << 4) + brow) * SQ
                                                + (kf << 4) + bcol) << 1));
                    bfr[2*j][0] = r4[0]; bfr[2*j][1] = r4[1];
                    bfr[2*j+1][0] = r4[2]; bfr[2*j+1][1] = r4[3];
                }
                #pragma unroll
                for (int nf = 0; nf < 8; ++nf) mma16816(sacc[nf], qh[kf], bfr[nf]);
                #pragma unroll
                for (int nf = 0; nf < 8; ++nf) mma16816h(cacc[nf], ql[kf], bfr[nf]);
            }
        }
        // fold f16 correction into f32 scores
        #pragma unroll
        for (int nf = 0; nf < 8; ++nf) {
            float2 c0 = __half22float2(*(__half2*)&cacc[nf][0]);
            float2 c1 = __half22float2(*(__half2*)&cacc[nf][1]);
            sacc[nf][0] += c0.x; sacc[nf][1] += c0.y;
            sacc[nf][2] += c1.x; sacc[nf][3] += c1.y;
        }

        // ---- masked online softmax; P -> A-frags in registers ----
        float m0 = -1e30f, m1 = -1e30f;
        #pragma unroll
        for (int nf = 0; nf < 8; ++nf) {
            unsigned w0 = mw0[nf >> 2], w1 = mw1[nf >> 2];
            int bb = ((nf & 3) << 3) + (tg << 1);
            m0 = fmaxf(m0, ((w0 >> bb) & 1u)       ? sacc[nf][0] : -1e30f);
            m0 = fmaxf(m0, ((w0 >> (bb + 1)) & 1u) ? sacc[nf][1] : -1e30f);
            m1 = fmaxf(m1, ((w1 >> bb) & 1u)       ? sacc[nf][2] : -1e30f);
            m1 = fmaxf(m1, ((w1 >> (bb + 1)) & 1u) ? sacc[nf][3] : -1e30f);
        }
        m0 = fmaxf(m0, __shfl_xor_sync(0xffffffffu, m0, 1));
        m0 = fmaxf(m0, __shfl_xor_sync(0xffffffffu, m0, 2));
        m1 = fmaxf(m1, __shfl_xor_sync(0xffffffffu, m1, 1));
        m1 = fmaxf(m1, __shfl_xor_sync(0xffffffffu, m1, 2));
        float mn0 = fmaxf(mr0, m0), mn1 = fmaxf(mr1, m1);
        float al0 = ex2((mr0 - mn0) * LOG2E), al1 = ex2((mr1 - mn1) * LOG2E);
        mr0 = mn0; mr1 = mn1;
        rs0 *= al0; rs1 *= al1;
        #pragma unroll
        for (int nf = 0; nf < 8; ++nf) {
            oacc[nf][0] *= al0; oacc[nf][1] *= al0;
            oacc[nf][2] *= al1; oacc[nf][3] *= al1;
        }
        const float mL0 = mn0 * LOG2E, mL1 = mn1 * LOG2E;
        uint32_t pa[4][4];
        #pragma unroll
        for (int k2 = 0; k2 < 4; ++k2) {
            int nfA = k2 << 1, nfB = nfA + 1;
            unsigned wA0 = mw0[nfA >> 2], wA1 = mw1[nfA >> 2];
            unsigned wB0 = mw0[nfB >> 2], wB1 = mw1[nfB >> 2];
            int bbA = ((nfA & 3) << 3) + (tg << 1);
            int bbB = ((nfB & 3) << 3) + (tg << 1);
            float p00 = ((wA0 >> bbA) & 1u)     ? ex2(fmaf(sacc[nfA][0], LOG2E, -mL0)) : 0.f;
            float p01 = ((wA0 >> (bbA+1)) & 1u) ? ex2(fmaf(sacc[nfA][1], LOG2E, -mL0)) : 0.f;
            float p02 = ((wA1 >> bbA) & 1u)     ? ex2(fmaf(sacc[nfA][2], LOG2E, -mL1)) : 0.f;
            float p03 = ((wA1 >> (bbA+1)) & 1u) ? ex2(fmaf(sacc[nfA][3], LOG2E, -mL1)) : 0.f;
            float p10 = ((wB0 >> bbB) & 1u)     ? ex2(fmaf(sacc[nfB][0], LOG2E, -mL0)) : 0.f;
            float p11 = ((wB0 >> (bbB+1)) & 1u) ? ex2(fmaf(sacc[nfB][1], LOG2E, -mL0)) : 0.f;
            float p12 = ((wB1 >> bbB) & 1u)     ? ex2(fmaf(sacc[nfB][2], LOG2E, -mL1)) : 0.f;
            float p13 = ((wB1 >> (bbB+1)) & 1u) ? ex2(fmaf(sacc[nfB][3], LOG2E, -mL1)) : 0.f;
            __half2 h0 = __floats2half2_rn(p00, p01);
            __half2 h1 = __floats2half2_rn(p02, p03);
            __half2 h2 = __floats2half2_rn(p10, p11);
            __half2 h3 = __floats2half2_rn(p12, p13);
            pa[k2][0] = *(uint32_t*)&h0; pa[k2][1] = *(uint32_t*)&h1;
            pa[k2][2] = *(uint32_t*)&h2; pa[k2][3] = *(uint32_t*)&h3;
            float2 f0 = __half22float2(h0), f2 = __half22float2(h2);
            float2 f1 = __half22float2(h1), f3 = __half22float2(h3);
            rs0 += (f0.x + f0.y) + (f2.x + f2.y);
            rs1 += (f1.x + f1.y) + (f3.x + f3.y);
        }

        // ---- GEMM-A: O += P * Vh ----
        {
            const int brow  = (((lane >> 3) & 1) << 3) + (lane & 7);
            const int bcolb = (lane >> 4) << 3;
            #pragma unroll
            for (int kf = 0; kf < 4; ++kf) {
                uint32_t bv[8][2];
                #pragma unroll
                for (int j = 0; j < 4; ++j) {
                    uint32_t r4[4];
                    ldsm4t(r4, kbH + ((uint32_t)(((kf << 4) + brow) * SQ
                                                 + (j << 4) + bcolb) << 1));
                    bv[2*j][0] = r4[0]; bv[2*j][1] = r4[1];
                    bv[2*j+1][0] = r4[2]; bv[2*j+1][1] = r4[3];
                }
                #pragma unroll
                for (int nf = 0; nf < 8; ++nf) mma16816(oacc[nf], pa[kf], bv[nf]);
            }
        }
        if (++buf == 3) buf = 0;
    }

    // ---- finalize ----
    rs0 += __shfl_xor_sync(0xffffffffu, rs0, 1);
    rs0 += __shfl_xor_sync(0xffffffffu, rs0, 2);
    rs1 += __shfl_xor_sync(0xffffffffu, rs1, 1);
    rs1 += __shfl_xor_sync(0xffffffffu, rs1, 2);
    float inv0 = 1.f / rs0, inv1 = 1.f / rs1;

    if (LAYER == 1) {
        int h = bh & (H_ - 1);
        int b = bh >> 2;
        size_t rbase = ((size_t)b * N_ + grow0) * HD_ + h * D_;
        #pragma unroll
        for (int nf = 0; nf < 8; ++nf) {
            int c = (nf << 3) + (tg << 1);
            float b0v = bias[h * D_ + c], b1v = bias[h * D_ + c + 1];
            float2 v0, v1;
            v0.x = lrelu(fmaf(oacc[nf][0], inv0, b0v));
            v0.y = lrelu(fmaf(oacc[nf][1], inv0, b1v));
            v1.x = lrelu(fmaf(oacc[nf][2], inv1, b0v));
            v1.y = lrelu(fmaf(oacc[nf][3], inv1, b1v));
            *(float2*)&g_z[rbase + c]           = v0;
            *(float2*)&g_z[rbase + 8 * HD_ + c] = v1;
        }
    } else {
        float v0[16], v1[16];
        float s0 = 0.f, s1 = 0.f;
        #pragma unroll
        for (int nf = 0; nf < 8; ++nf) {
            int c = (nf << 3) + (tg << 1);
            float b0v = bias[c], b1v = bias[c + 1];
            float a;
            a = lrelu(fmaf(oacc[nf][0], inv0, b0v)); v0[2*nf]   = a; s0 += a;
            a = lrelu(fmaf(oacc[nf][1], inv0, b1v)); v0[2*nf+1] = a; s0 += a;
            a = lrelu(fmaf(oacc[nf][2], inv1, b0v)); v1[2*nf]   = a; s1 += a;
            a = lrelu(fmaf(oacc[nf][3], inv1, b1v)); v1[2*nf+1] = a; s1 += a;
        }
        s0 += __shfl_xor_sync(0xffffffffu, s0, 1);
        s0 += __shfl_xor_sync(0xffffffffu, s0, 2);
        s1 += __shfl_xor_sync(0xffffffffu, s1, 1);
        s1 += __shfl_xor_sync(0xffffffffu, s1, 2);
        float mu0 = s0 * (1.f / 64.f), mu1 = s1 * (1.f / 64.f);
        float q0 = 0.f, q1 = 0.f;
        #pragma unroll
        for (int i = 0; i < 16; ++i) {
            float u0 = v0[i] - mu0; q0 += u0 * u0;
            float u1 = v1[i] - mu1; q1 += u1 * u1;
        }
        q0 += __shfl_xor_sync(0xffffffffu, q0, 1);
        q0 += __shfl_xor_sync(0xffffffffu, q0, 2);
        q1 += __shfl_xor_sync(0xffffffffu, q1, 1);
        q1 += __shfl_xor_sync(0xffffffffu, q1, 2);
        float rstd0 = rsqrtf(q0 * (1.f / 64.f) + 1e-5f);
        float rstd1 = rsqrtf(q1 * (1.f / 64.f) + 1e-5f);
        float* od0 = outp + ((size_t)bh * N_ + grow0) * D_;
        float* od1 = od0 + 8 * D_;
        #pragma unroll
        for (int nf = 0; nf < 8; ++nf) {
            int c = (nf << 3) + (tg << 1);
            float ga0 = gamma[c], ga1 = gamma[c + 1];
            float be0 = beta[c],  be1 = beta[c + 1];
            float2 w0, w1;
            w0.x = (v0[2*nf]   - mu0) * rstd0 * ga0 + be0;
            w0.y = (v0[2*nf+1] - mu0) * rstd0 * ga1 + be1;
            w1.x = (v1[2*nf]   - mu1) * rstd1 * ga0 + be0;
            w1.y = (v1[2*nf+1] - mu1) * rstd1 * ga1 + be1;
            *(float2*)&od0[c] = w0;
            *(float2*)&od1[c] = w1;
        }
    }
}

// ---------------- launch -----------------------------------------------------
extern "C" void kernel_launch(void* const* d_in, const int* in_sizes, int n_in,
                              void* d_out, int out_size) {
    const float* x     = (const float*)d_in[0];
    const int*   graph = (const int*)  d_in[1];
    const float* Wh    = (const float*)d_in[2];
    const float* bh    = (const float*)d_in[3];
    const float* Wo    = (const float*)d_in[4];
    const float* bo    = (const float*)d_in[5];
    const float* gamma = (const float*)d_in[6];
    const float* beta  = (const float*)d_in[7];
    float* out = (float*)d_out;

    cudaFuncSetAttribute(attn_mma<1>, cudaFuncAttributeMaxDynamicSharedMemorySize, SMEM_ATT);
    cudaFuncSetAttribute(attn_mma<2>, cudaFuncAttributeMaxDynamicSharedMemorySize, SMEM_ATT);

    build_mask_kernel<<<(N_ * NW_) / 8, 256>>>(graph);
    proj1_kernel<<<dim3(B_ * N_ / 64, H_), 256>>>(x, Wh);
    attn_mma<1><<<dim3(B_ * H_, N_ / 64), 128, SMEM_ATT>>>(bh, nullptr, nullptr, nullptr);
    proj2_kernel<<<(B_ * N_) / 32, 256>>>(Wo);
    attn_mma<2><<<dim3(B_, N_ / 64), 128, SMEM_ATT>>>(bo, gamma, beta, out);
}

// round 13
// speedup vs baseline: 1.0386x; 1.0386x over previous
#include <cuda_runtime.h>
#include <cuda_fp16.h>
#include <cstdint>

// Problem shape (fixed for this registry entry)
#define B_  8
#define N_  2048
#define C_  64
#define H_  4
#define D_  64
#define HD_ 256          // H*D
#define NW_ (N_/32)      // mask words per row = 64
#define LOG2E 1.4426950408889634f

// ---------------- scratch (device globals: no allocation allowed) -----------
__device__ __half  g_hH [B_*H_*N_*D_];    // layer1 features, f16 hi
__device__ __half  g_hL [B_*H_*N_*D_];    // layer1 features, f16 lo (residual)
__device__ __half  g_h2H[B_*N_*D_];       // layer2 features hi
__device__ __half  g_h2L[B_*N_*D_];       // layer2 features lo
__device__ float   g_h2p[B_*H_*N_*D_];    // per-head partial h2 (deterministic, no atomics)
__device__ __half  g_WoH[D_*HD_];         // Wo f16 hi
__device__ __half  g_WoL[D_*HD_];         // Wo f16 lo
__device__ unsigned g_maskT[NW_*N_];      // transposed bitmask [w][n]

__device__ __forceinline__ float ex2(float x) {
    float y;
    asm("ex2.approx.f32 %0, %1;" : "=f"(y) : "f"(x));
    return y;
}
__device__ __forceinline__ uint32_t smem_u32(const void* p) {
    uint32_t a;
    asm("{ .reg .u64 t; cvta.to.shared.u64 t, %1; cvt.u32.u64 %0, t; }" : "=r"(a) : "l"(p));
    return a;
}
__device__ __forceinline__ void cp16(uint32_t saddr, const void* g) {
    asm volatile("cp.async.ca.shared.global [%0], [%1], 16;"
                 :: "r"(saddr), "l"(__cvta_generic_to_global(g)));
}
__device__ __forceinline__ void ldsm4(uint32_t r[4], uint32_t addr) {
    asm volatile("ldmatrix.sync.aligned.m8n8.x4.shared.b16 {%0,%1,%2,%3}, [%4];"
                 : "=r"(r[0]), "=r"(r[1]), "=r"(r[2]), "=r"(r[3]) : "r"(addr));
}
__device__ __forceinline__ void ldsm4t(uint32_t r[4], uint32_t addr) {
    asm volatile("ldmatrix.sync.aligned.m8n8.x4.trans.shared.b16 {%0,%1,%2,%3}, [%4];"
                 : "=r"(r[0]), "=r"(r[1]), "=r"(r[2]), "=r"(r[3]) : "r"(addr));
}
__device__ __forceinline__ void mma16816(float d[4], const uint32_t a[4], const uint32_t b[2]) {
    asm volatile("mma.sync.aligned.m16n8k16.row.col.f32.f16.f16.f32 "
                 "{%0,%1,%2,%3}, {%4,%5,%6,%7}, {%8,%9}, {%0,%1,%2,%3};"
                 : "+f"(d[0]), "+f"(d[1]), "+f"(d[2]), "+f"(d[3])
                 : "r"(a[0]), "r"(a[1]), "r"(a[2]), "r"(a[3]), "r"(b[0]), "r"(b[1]));
}
__device__ __forceinline__ float lrelu(float a) { return a > 0.f ? a : 0.2f * a; }

__device__ __forceinline__ void split_store(__half* dH, __half* dL, size_t idx,
                                            float v0, float v1) {
    __half h0 = __float2half_rn(v0), h1 = __float2half_rn(v1);
    __half l0 = __float2half_rn(v0 - __half2float(h0));
    __half l1 = __float2half_rn(v1 - __half2float(h1));
    *(__half2*)&dH[idx] = __halves2half2(h0, h1);
    *(__half2*)&dL[idx] = __halves2half2(l0, l1);
}

// ---------------- one-time Wo f16 hi/lo split (64x256 = 16384 elems) --------
__global__ void convert_wo_kernel(const float* __restrict__ Wo) {
    int i = blockIdx.x * 256 + threadIdx.x;
    float w = Wo[i];
    __half hh = __float2half_rn(w);
    g_WoH[i] = hh;
    g_WoL[i] = __float2half_rn(w - __half2float(hh));
}

// ---------------- mask build ------------------------------------------------
__global__ void build_mask_kernel(const int* __restrict__ graph) {
    int gwarp = (blockIdx.x * blockDim.x + threadIdx.x) >> 5;
    int lane  = threadIdx.x & 31;
    if (gwarp >= N_ * NW_) return;
    int n = gwarp >> 6;
    int w = gwarp & (NW_ - 1);
    int m = w * 32 + lane;
    bool bit = (graph[(size_t)n * N_ + m] != 0) || (m == n);
    unsigned word = __ballot_sync(0xffffffffu, bit);
    if (lane == 0) g_maskT[w * N_ + n] = word;
}

// ---------------- proj1: one head per blockIdx.y (grid 256 x 4) -------------
__global__ void proj1_kernel(const float* __restrict__ x,
                             const float* __restrict__ Wh) {
    __shared__ float xs[64][65];
    __shared__ float ws[64][65];
    int t    = threadIdx.x;              // 256 threads
    int row0 = blockIdx.x * 64;          // flattened b*N + n
    int h    = blockIdx.y;
    for (int i = t; i < 64 * 64; i += 256) {
        int r = i >> 6, c = i & 63;
        xs[r][c] = x[(size_t)(row0 + r) * C_ + c];
        ws[r][c] = Wh[((size_t)h * D_ + r) * C_ + c];
    }
    __syncthreads();
    int d0 = (t & 15) * 4;
    int r0 = (t >> 4) * 4;
    int b     = row0 >> 11;
    int nbase = row0 & (N_ - 1);
    float acc[4][4] = {};
    #pragma unroll 8
    for (int c = 0; c < 64; ++c) {
        float xv[4], wv[4];
        #pragma unroll
        for (int i = 0; i < 4; ++i) { xv[i] = xs[r0 + i][c]; wv[i] = ws[d0 + i][c]; }
        #pragma unroll
        for (int i = 0; i < 4; ++i)
            #pragma unroll
            for (int j = 0; j < 4; ++j)
                acc[i][j] += xv[i] * wv[j];
    }
    #pragma unroll
    for (int i = 0; i < 4; ++i) {
        size_t base = (((size_t)(b * H_ + h) * N_) + nbase + r0 + i) * D_ + d0;
        split_store(g_hH, g_hL, base,     acc[i][0], acc[i][1]);
        split_store(g_hH, g_hL, base + 2, acc[i][2], acc[i][3]);
    }
}

// ---------------- reduce_h2: sum 4 head partials, split to f16 hi/lo --------
__global__ void reduce_h2_kernel() {
    int idx = blockIdx.x * 256 + threadIdx.x;    // 0 .. B*N*32-1 (float2 units)
    int d2 = idx & 31;
    int n  = (idx >> 5) & (N_ - 1);
    int b  = idx >> 16;                          // idx / (32*2048)
    float2 s = make_float2(0.f, 0.f);
    #pragma unroll
    for (int h = 0; h < H_; ++h) {
        float2 v = *(const float2*)&g_h2p[(((size_t)(b * H_ + h) * N_) + n) * D_ + d2 * 2];
        s.x += v.x; s.y += v.y;
    }
    split_store(g_h2H, g_h2L, ((size_t)(b * N_ + n)) * D_ + d2 * 2, s.x, s.y);
}

// ================= HMMA flash attention, 4 warps / 64 rows ===================
// KV tile = 64 cols, 3-deep cp.async ring (KH only), 3 blocks/SM.
// S = Qh*Kh + Ql*Kh (both f32-acc), P f16, O = P*Vh.
// LAYER 1 epilogue: lrelu(z) -> f16 hi/lo A-frags -> 3-term MMA with Wo head
// slice (staged into dead K-ring smem) -> per-head partial h2 (no atomics).
#define SQ 72                          // smem row stride in halves
#define NT 32                          // KV tiles
#define SM_QH 0
#define SM_QL 4608
#define SM_K  9216                     // ring starts after QH/QL
#define KBUF_HALVES 4608               // KH[64][72]
#define SMEM_ATT ((9216 + 3 * KBUF_HALVES) * 2)   // 46080 bytes

template <int LAYER>
__global__ void __launch_bounds__(128, 3)
attn_mma(const float* __restrict__ bias,
         const float* __restrict__ gamma,
         const float* __restrict__ beta,
         float* __restrict__ outp) {
    extern __shared__ __half smh[];
    const int t    = threadIdx.x;
    const int wid  = t >> 5;            // 0..3
    const int lane = t & 31;
    const int g    = lane >> 2;
    const int tg   = lane & 3;
    const int wr0  = wid << 4;
    const int bh   = blockIdx.x;
    const int row0 = blockIdx.y << 6;   // 64 query rows per block
    const __half* hH = (LAYER == 1 ? g_hH : g_h2H) + (size_t)bh * (N_ * D_);
    const __half* hL = (LAYER == 1 ? g_hL : g_h2L) + (size_t)bh * (N_ * D_);
    const uint32_t sbase = smem_u32(smh);

    // ---- stage Q hi + lo (64 rows) via plain loads ----
    {
        const uint4* sH = (const uint4*)(hH + (size_t)row0 * D_);
        const uint4* sL = (const uint4*)(hL + (size_t)row0 * D_);
        #pragma unroll
        for (int i = 0; i < 4; ++i) {
            int idx = t + (i << 7);            // 0..511
            int r = idx >> 3, c8 = (idx & 7) << 3;
            *(uint4*)&smh[SM_QH + r * SQ + c8] = sH[idx];
            *(uint4*)&smh[SM_QL + r * SQ + c8] = sL[idx];
        }
    }
    // ---- prefetch K tiles 0,1 (hi only) into ring buffers 0,1 ----
    #pragma unroll
    for (int pt = 0; pt < 2; ++pt) {
        const uint4* sH = (const uint4*)(hH + (size_t)pt * (64 * D_));
        uint32_t kb = sbase + (uint32_t)(SM_K + pt * KBUF_HALVES) * 2;
        #pragma unroll
        for (int i = 0; i < 4; ++i) {
            int idx = t + (i << 7);            // 0..511
            int r = idx >> 3, c8 = (idx & 7) << 3;
            cp16(kb + (((uint32_t)(r * SQ + c8)) << 1), sH + idx);
        }
        asm volatile("cp.async.commit_group;" ::: "memory");
    }
    __syncthreads();

    // ---- preload Q A-frags (hi and lo) ----
    uint32_t qh[4][4], ql[4][4];
    {
        int arow  = wr0 + (lane & 15);
        int acolb = (lane >> 4) << 3;
        #pragma unroll
        for (int kf = 0; kf < 4; ++kf) {
            ldsm4(qh[kf], sbase + ((uint32_t)(SM_QH + arow * SQ + (kf << 4) + acolb) << 1));
            ldsm4(ql[kf], sbase + ((uint32_t)(SM_QL + arow * SQ + (kf << 4) + acolb) << 1));
        }
    }

    float oacc[8][4];
    #pragma unroll
    for (int i = 0; i < 8; ++i)
        #pragma unroll
        for (int j = 0; j < 4; ++j) oacc[i][j] = 0.f;
    float rs0 = 0.f, rs1 = 0.f, mr0 = -1e30f, mr1 = -1e30f;
    const int grow0 = row0 + wr0 + g;

    int buf = 0;
    #pragma unroll 1
    for (int tile = 0; tile < NT; ++tile) {
        asm volatile("cp.async.wait_group 1;" ::: "memory");
        __syncthreads();
        // ---- prefetch tile+2 into ring slot ----
        {
            int pt = tile + 2;
            if (pt < NT) {
                int pb = buf + 2; if (pb >= 3) pb -= 3;
                const uint4* sH = (const uint4*)(hH + (size_t)pt * (64 * D_));
                uint32_t kb = sbase + (uint32_t)(SM_K + pb * KBUF_HALVES) * 2;
                #pragma unroll
                for (int i = 0; i < 4; ++i) {
                    int idx = t + (i << 7);
                    int r = idx >> 3, c8 = (idx & 7) << 3;
                    cp16(kb + (((uint32_t)(r * SQ + c8)) << 1), sH + idx);
                }
            }
            asm volatile("cp.async.commit_group;" ::: "memory");   // empty group ok
        }
        unsigned mw0[2], mw1[2];
        #pragma unroll
        for (int w = 0; w < 2; ++w) {
            mw0[w] = g_maskT[(size_t)((tile << 1) + w) * N_ + grow0];
            mw1[w] = g_maskT[(size_t)((tile << 1) + w) * N_ + grow0 + 8];
        }

        const uint32_t kbH = sbase + (uint32_t)(SM_K + buf * KBUF_HALVES) * 2;

        // ---- GEMM-S: sacc = Qh*Kh + Ql*Kh ; K frags reused for both terms --
        float sacc[8][4];
        #pragma unroll
        for (int i = 0; i < 8; ++i)
            #pragma unroll
            for (int j = 0; j < 4; ++j) sacc[i][j] = 0.f;
        {
            const int brow = ((lane >> 4) << 3) + (lane & 7);
            const int bcol = ((lane >> 3) & 1) << 3;
            #pragma unroll
            for (int kf = 0; kf < 4; ++kf) {
                uint32_t bfr[8][2];
                #pragma unroll
                for (int j = 0; j < 4; ++j) {
                    uint32_t r4[4];
                    ldsm4(r4, kbH + ((uint32_t)(((j << 4) + brow) * SQ
                                                + (kf << 4) + bcol) << 1));
                    bfr[2*j][0] = r4[0]; bfr[2*j][1] = r4[1];
                    bfr[2*j+1][0] = r4[2]; bfr[2*j+1][1] = r4[3];
                }
                #pragma unroll
                for (int nf = 0; nf < 8; ++nf) mma16816(sacc[nf], qh[kf], bfr[nf]);
                #pragma unroll
                for (int nf = 0; nf < 8; ++nf) mma16816(sacc[nf], ql[kf], bfr[nf]);
            }
        }

        // ---- masked online softmax; P -> A-frags in registers ----
        float m0 = -1e30f, m1 = -1e30f;
        #pragma unroll
        for (int nf = 0; nf < 8; ++nf) {
            unsigned w0 = mw0[nf >> 2], w1 = mw1[nf >> 2];
            int bb = ((nf & 3) << 3) + (tg << 1);
            m0 = fmaxf(m0, ((w0 >> bb) & 1u)       ? sacc[nf][0] : -1e30f);
            m0 = fmaxf(m0, ((w0 >> (bb + 1)) & 1u) ? sacc[nf][1] : -1e30f);
            m1 = fmaxf(m1, ((w1 >> bb) & 1u)       ? sacc[nf][2] : -1e30f);
            m1 = fmaxf(m1, ((w1 >> (bb + 1)) & 1u) ? sacc[nf][3] : -1e30f);
        }
        m0 = fmaxf(m0, __shfl_xor_sync(0xffffffffu, m0, 1));
        m0 = fmaxf(m0, __shfl_xor_sync(0xffffffffu, m0, 2));
        m1 = fmaxf(m1, __shfl_xor_sync(0xffffffffu, m1, 1));
        m1 = fmaxf(m1, __shfl_xor_sync(0xffffffffu, m1, 2));
        float mn0 = fmaxf(mr0, m0), mn1 = fmaxf(mr1, m1);
        float al0 = ex2((mr0 - mn0) * LOG2E), al1 = ex2((mr1 - mn1) * LOG2E);
        mr0 = mn0; mr1 = mn1;
        rs0 *= al0; rs1 *= al1;
        #pragma unroll
        for (int nf = 0; nf < 8; ++nf) {
            oacc[nf][0] *= al0; oacc[nf][1] *= al0;
            oacc[nf][2] *= al1; oacc[nf][3] *= al1;
        }
        const float mL0 = mn0 * LOG2E, mL1 = mn1 * LOG2E;
        uint32_t pa[4][4];
        #pragma unroll
        for (int k2 = 0; k2 < 4; ++k2) {
            int nfA = k2 << 1, nfB = nfA + 1;
            unsigned wA0 = mw0[nfA >> 2], wA1 = mw1[nfA >> 2];
            unsigned wB0 = mw0[nfB >> 2], wB1 = mw1[nfB >> 2];
            int bbA = ((nfA & 3) << 3) + (tg << 1);
            int bbB = ((nfB & 3) << 3) + (tg << 1);
            float p00 = ((wA0 >> bbA) & 1u)     ? ex2(fmaf(sacc[nfA][0], LOG2E, -mL0)) : 0.f;
            float p01 = ((wA0 >> (bbA+1)) & 1u) ? ex2(fmaf(sacc[nfA][1], LOG2E, -mL0)) : 0.f;
            float p02 = ((wA1 >> bbA) & 1u)     ? ex2(fmaf(sacc[nfA][2], LOG2E, -mL1)) : 0.f;
            float p03 = ((wA1 >> (bbA+1)) & 1u) ? ex2(fmaf(sacc[nfA][3], LOG2E, -mL1)) : 0.f;
            float p10 = ((wB0 >> bbB) & 1u)     ? ex2(fmaf(sacc[nfB][0], LOG2E, -mL0)) : 0.f;
            float p11 = ((wB0 >> (bbB+1)) & 1u) ? ex2(fmaf(sacc[nfB][1], LOG2E, -mL0)) : 0.f;
            float p12 = ((wB1 >> bbB) & 1u)     ? ex2(fmaf(sacc[nfB][2], LOG2E, -mL1)) : 0.f;
            float p13 = ((wB1 >> (bbB+1)) & 1u) ? ex2(fmaf(sacc[nfB][3], LOG2E, -mL1)) : 0.f;
            __half2 h0 = __floats2half2_rn(p00, p01);
            __half2 h1 = __floats2half2_rn(p02, p03);
            __half2 h2 = __floats2half2_rn(p10, p11);
            __half2 h3 = __floats2half2_rn(p12, p13);
            pa[k2][0] = *(uint32_t*)&h0; pa[k2][1] = *(uint32_t*)&h1;
            pa[k2][2] = *(uint32_t*)&h2; pa[k2][3] = *(uint32_t*)&h3;
            float2 f0 = __half22float2(h0), f2 = __half22float2(h2);
            float2 f1 = __half22float2(h1), f3 = __half22float2(h3);
            rs0 += (f0.x + f0.y) + (f2.x + f2.y);
            rs1 += (f1.x + f1.y) + (f3.x + f3.y);
        }

        // ---- GEMM-A: O += P * Vh ----
        {
            const int brow  = (((lane >> 3) & 1) << 3) + (lane & 7);
            const int bcolb = (lane >> 4) << 3;
            #pragma unroll
            for (int kf = 0; kf < 4; ++kf) {
                uint32_t bv[8][2];
                #pragma unroll
                for (int j = 0; j < 4; ++j) {
                    uint32_t r4[4];
                    ldsm4t(r4, kbH + ((uint32_t)(((kf << 4) + brow) * SQ
                                                 + (j << 4) + bcolb) << 1));
                    bv[2*j][0] = r4[0]; bv[2*j][1] = r4[1];
                    bv[2*j+1][0] = r4[2]; bv[2*j+1][1] = r4[3];
                }
                #pragma unroll
                for (int nf = 0; nf < 8; ++nf) mma16816(oacc[nf], pa[kf], bv[nf]);
            }
        }
        if (++buf == 3) buf = 0;
    }

    // ---- finalize: rowsum quad-reduce ----
    rs0 += __shfl_xor_sync(0xffffffffu, rs0, 1);
    rs0 += __shfl_xor_sync(0xffffffffu, rs0, 2);
    rs1 += __shfl_xor_sync(0xffffffffu, rs1, 1);
    rs1 += __shfl_xor_sync(0xffffffffu, rs1, 2);
    float inv0 = 1.f / rs0, inv1 = 1.f / rs1;

    if (LAYER == 1) {
        // ---- fused proj2 slice: h2_partial = lrelu(z_slice) @ Wo_slice^T ----
        const int h = bh & (H_ - 1);
        // z values + f16 hi/lo split in registers
        float zv[8][4];
        #pragma unroll
        for (int nf = 0; nf < 8; ++nf) {
            int c = (nf << 3) + (tg << 1);
            float b0v = bias[h * D_ + c], b1v = bias[h * D_ + c + 1];
            zv[nf][0] = lrelu(fmaf(oacc[nf][0], inv0, b0v));
            zv[nf][1] = lrelu(fmaf(oacc[nf][1], inv0, b1v));
            zv[nf][2] = lrelu(fmaf(oacc[nf][2], inv1, b0v));
            zv[nf][3] = lrelu(fmaf(oacc[nf][3], inv1, b1v));
        }
        uint32_t zh[4][4], zl[4][4];
        #pragma unroll
        for (int kf = 0; kf < 4; ++kf) {
            int nfA = kf << 1, nfB = nfA + 1;
            __half2 hA0 = __floats2half2_rn(zv[nfA][0], zv[nfA][1]);
            __half2 hA1 = __floats2half2_rn(zv[nfA][2], zv[nfA][3]);
            __half2 hB0 = __floats2half2_rn(zv[nfB][0], zv[nfB][1]);
            __half2 hB1 = __floats2half2_rn(zv[nfB][2], zv[nfB][3]);
            float2 fA0 = __half22float2(hA0), fA1 = __half22float2(hA1);
            float2 fB0 = __half22float2(hB0), fB1 = __half22float2(hB1);
            __half2 lA0 = __floats2half2_rn(zv[nfA][0] - fA0.x, zv[nfA][1] - fA0.y);
            __half2 lA1 = __floats2half2_rn(zv[nfA][2] - fA1.x, zv[nfA][3] - fA1.y);
            __half2 lB0 = __floats2half2_rn(zv[nfB][0] - fB0.x, zv[nfB][1] - fB0.y);
            __half2 lB1 = __floats2half2_rn(zv[nfB][2] - fB1.x, zv[nfB][3] - fB1.y);
            zh[kf][0] = *(uint32_t*)&hA0; zh[kf][1] = *(uint32_t*)&hA1;
            zh[kf][2] = *(uint32_t*)&hB0; zh[kf][3] = *(uint32_t*)&hB1;
            zl[kf][0] = *(uint32_t*)&lA0; zl[kf][1] = *(uint32_t*)&lA1;
            zl[kf][2] = *(uint32_t*)&lB0; zl[kf][3] = *(uint32_t*)&lB1;
        }
        // stage Wo head slice (hi at SM_K, lo at SM_K+KBUF) into dead ring smem
        __syncthreads();   // all warps done with K ring
        #pragma unroll
        for (int i = 0; i < 4; ++i) {
            int idx = t + (i << 7);            // 0..511
            int r = idx >> 3, c8 = (idx & 7) << 3;
            *(uint4*)&smh[SM_K + r * SQ + c8] =
                *(const uint4*)(g_WoH + (size_t)r * HD_ + h * D_ + c8);
            *(uint4*)&smh[SM_K + KBUF_HALVES + r * SQ + c8] =
                *(const uint4*)(g_WoL + (size_t)r * HD_ + h * D_ + c8);
        }
        __syncthreads();
        // 3-term MMA: zh*WoH + zl*WoH + zh*WoL (B layout identical to GEMM-S)
        float o2[8][4];
        #pragma unroll
        for (int i = 0; i < 8; ++i)
            #pragma unroll
            for (int j = 0; j < 4; ++j) o2[i][j] = 0.f;
        {
            const int brow = ((lane >> 4) << 3) + (lane & 7);
            const int bcol = ((lane >> 3) & 1) << 3;
            const uint32_t wbH = sbase + (uint32_t)SM_K * 2;
            const uint32_t wbL = wbH + ((uint32_t)KBUF_HALVES << 1);
            #pragma unroll
            for (int kf = 0; kf < 4; ++kf) {
                uint32_t bfr[8][2];
                #pragma unroll
                for (int j = 0; j < 4; ++j) {
                    uint32_t r4[4];
                    ldsm4(r4, wbH + ((uint32_t)(((j << 4) + brow) * SQ
                                                + (kf << 4) + bcol) << 1));
                    bfr[2*j][0] = r4[0]; bfr[2*j][1] = r4[1];
                    bfr[2*j+1][0] = r4[2]; bfr[2*j+1][1] = r4[3];
                }
                #pragma unroll
                for (int nf = 0; nf < 8; ++nf) mma16816(o2[nf], zh[kf], bfr[nf]);
                #pragma unroll
                for (int nf = 0; nf < 8; ++nf) mma16816(o2[nf], zl[kf], bfr[nf]);
                #pragma unroll
                for (int j = 0; j < 4; ++j) {
                    uint32_t r4[4];
                    ldsm4(r4, wbL + ((uint32_t)(((j << 4) + brow) * SQ
                                                + (kf << 4) + bcol) << 1));
                    bfr[2*j][0] = r4[0]; bfr[2*j][1] = r4[1];
                    bfr[2*j+1][0] = r4[2]; bfr[2*j+1][1] = r4[3];
                }
                #pragma unroll
                for (int nf = 0; nf < 8; ++nf) mma16816(o2[nf], zh[kf], bfr[nf]);
            }
        }
        // write per-head partial h2 (unique writer per slot — deterministic)
        size_t rb = ((size_t)bh * N_ + grow0) * D_;
        #pragma unroll
        for (int nf = 0; nf < 8; ++nf) {
            int d = (nf << 3) + (tg << 1);
            *(float2*)&g_h2p[rb + d]           = make_float2(o2[nf][0], o2[nf][1]);
            *(float2*)&g_h2p[rb + 8 * D_ + d]  = make_float2(o2[nf][2], o2[nf][3]);
        }
    } else {
        float v0[16], v1[16];
        float s0 = 0.f, s1 = 0.f;
        #pragma unroll
        for (int nf = 0; nf < 8; ++nf) {
            int c = (nf << 3) + (tg << 1);
            float b0v = bias[c], b1v = bias[c + 1];
            float a;
            a = lrelu(fmaf(oacc[nf][0], inv0, b0v)); v0[2*nf]   = a; s0 += a;
            a = lrelu(fmaf(oacc[nf][1], inv0, b1v)); v0[2*nf+1] = a; s0 += a;
            a = lrelu(fmaf(oacc[nf][2], inv1, b0v)); v1[2*nf]   = a; s1 += a;
            a = lrelu(fmaf(oacc[nf][3], inv1, b1v)); v1[2*nf+1] = a; s1 += a;
        }
        s0 += __shfl_xor_sync(0xffffffffu, s0, 1);
        s0 += __shfl_xor_sync(0xffffffffu, s0, 2);
        s1 += __shfl_xor_sync(0xffffffffu, s1, 1);
        s1 += __shfl_xor_sync(0xffffffffu, s1, 2);
        float mu0 = s0 * (1.f / 64.f), mu1 = s1 * (1.f / 64.f);
        float q0 = 0.f, q1 = 0.f;
        #pragma unroll
        for (int i = 0; i < 16; ++i) {
            float u0 = v0[i] - mu0; q0 += u0 * u0;
            float u1 = v1[i] - mu1; q1 += u1 * u1;
        }
        q0 += __shfl_xor_sync(0xffffffffu, q0, 1);
        q0 += __shfl_xor_sync(0xffffffffu, q0, 2);
        q1 += __shfl_xor_sync(0xffffffffu, q1, 1);
        q1 += __shfl_xor_sync(0xffffffffu, q1, 2);
        float rstd0 = rsqrtf(q0 * (1.f / 64.f) + 1e-5f);
        float rstd1 = rsqrtf(q1 * (1.f / 64.f) + 1e-5f);
        float* od0 = outp + ((size_t)bh * N_ + grow0) * D_;
        float* od1 = od0 + 8 * D_;
        #pragma unroll
        for (int nf = 0; nf < 8; ++nf) {
            int c = (nf << 3) + (tg << 1);
            float ga0 = gamma[c], ga1 = gamma[c + 1];
            float be0 = beta[c],  be1 = beta[c + 1];
            float2 w0, w1;
            w0.x = (v0[2*nf]   - mu0) * rstd0 * ga0 + be0;
            w0.y = (v0[2*nf+1] - mu0) * rstd0 * ga1 + be1;
            w1.x = (v1[2*nf]   - mu1) * rstd1 * ga0 + be0;
            w1.y = (v1[2*nf+1] - mu1) * rstd1 * ga1 + be1;
            *(float2*)&od0[c] = w0;
            *(float2*)&od1[c] = w1;
        }
    }
}

// ---------------- launch -----------------------------------------------------
extern "C" void kernel_launch(void* const* d_in, const int* in_sizes, int n_in,
                              void* d_out, int out_size) {
    const float* x     = (const float*)d_in[0];
    const int*   graph = (const int*)  d_in[1];
    const float* Wh    = (const float*)d_in[2];
    const float* bh    = (const float*)d_in[3];
    const float* Wo    = (const float*)d_in[4];
    const float* bo    = (const float*)d_in[5];
    const float* gamma = (const float*)d_in[6];
    const float* beta  = (const float*)d_in[7];
    float* out = (float*)d_out;

    cudaFuncSetAttribute(attn_mma<1>, cudaFuncAttributeMaxDynamicSharedMemorySize, SMEM_ATT);
    cudaFuncSetAttribute(attn_mma<2>, cudaFuncAttributeMaxDynamicSharedMemorySize, SMEM_ATT);

    convert_wo_kernel<<<64, 256>>>(Wo);
    build_mask_kernel<<<(N_ * NW_) / 8, 256>>>(graph);
    proj1_kernel<<<dim3(B_ * N_ / 64, H_), 256>>>(x, Wh);
    attn_mma<1><<<dim3(B_ * H_, N_ / 64), 128, SMEM_ATT>>>(bh, nullptr, nullptr, nullptr);
    reduce_h2_kernel<<<(B_ * N_ * 32) / 256, 256>>>();
    attn_mma<2><<<dim3(B_, N_ / 64), 128, SMEM_ATT>>>(bo, gamma, beta, out);
}

// round 14
// speedup vs baseline: 1.1500x; 1.1072x over previous
#include <cuda_runtime.h>
#include <cuda_fp16.h>
#include <cstdint>

// Problem shape (fixed for this registry entry)
#define B_  8
#define N_  2048
#define C_  64
#define H_  4
#define D_  64
#define HD_ 256          // H*D
#define NW_ (N_/32)      // mask words per row = 64
#define LOG2E 1.4426950408889634f

// ---------------- scratch (device globals: no allocation allowed) -----------
__device__ __half  g_hH [B_*H_*N_*D_];    // layer1 features, f16 hi
__device__ __half  g_hL [B_*H_*N_*D_];    // layer1 features, f16 lo (residual)
__device__ __half  g_h2H[B_*N_*D_];       // layer2 features hi
__device__ __half  g_h2L[B_*N_*D_];       // layer2 features lo
__device__ float   g_h2p[B_*H_*N_*D_];    // per-head partial h2 (deterministic)
__device__ __half  g_WoH[D_*HD_];         // Wo f16 hi
__device__ __half  g_WoL[D_*HD_];         // Wo f16 lo
__device__ unsigned g_maskT[NW_*N_];      // transposed bitmask [w][n]

__device__ __forceinline__ float ex2(float x) {
    float y;
    asm("ex2.approx.f32 %0, %1;" : "=f"(y) : "f"(x));
    return y;
}
__device__ __forceinline__ uint32_t smem_u32(const void* p) {
    uint32_t a;
    asm("{ .reg .u64 t; cvta.to.shared.u64 t, %1; cvt.u32.u64 %0, t; }" : "=r"(a) : "l"(p));
    return a;
}
__device__ __forceinline__ void cp16(uint32_t saddr, const void* g) {
    asm volatile("cp.async.ca.shared.global [%0], [%1], 16;"
                 :: "r"(saddr), "l"(__cvta_generic_to_global(g)));
}
__device__ __forceinline__ void ldsm4(uint32_t r[4], uint32_t addr) {
    asm volatile("ldmatrix.sync.aligned.m8n8.x4.shared.b16 {%0,%1,%2,%3}, [%4];"
                 : "=r"(r[0]), "=r"(r[1]), "=r"(r[2]), "=r"(r[3]) : "r"(addr));
}
__device__ __forceinline__ void ldsm4t(uint32_t r[4], uint32_t addr) {
    asm volatile("ldmatrix.sync.aligned.m8n8.x4.trans.shared.b16 {%0,%1,%2,%3}, [%4];"
                 : "=r"(r[0]), "=r"(r[1]), "=r"(r[2]), "=r"(r[3]) : "r"(addr));
}
__device__ __forceinline__ void mma16816(float d[4], const uint32_t a[4], const uint32_t b[2]) {
    asm volatile("mma.sync.aligned.m16n8k16.row.col.f32.f16.f16.f32 "
                 "{%0,%1,%2,%3}, {%4,%5,%6,%7}, {%8,%9}, {%0,%1,%2,%3};"
                 : "+f"(d[0]), "+f"(d[1]), "+f"(d[2]), "+f"(d[3])
                 : "r"(a[0]), "r"(a[1]), "r"(a[2]), "r"(a[3]), "r"(b[0]), "r"(b[1]));
}
__device__ __forceinline__ float lrelu(float a) { return a > 0.f ? a : 0.2f * a; }

__device__ __forceinline__ void split_store(__half* dH, __half* dL, size_t idx,
                                            float v0, float v1) {
    __half h0 = __float2half_rn(v0), h1 = __float2half_rn(v1);
    __half l0 = __float2half_rn(v0 - __half2float(h0));
    __half l1 = __float2half_rn(v1 - __half2float(h1));
    *(__half2*)&dH[idx] = __halves2half2(h0, h1);
    *(__half2*)&dL[idx] = __halves2half2(l0, l1);
}

// ---------------- one-time Wo f16 hi/lo split --------------------------------
__global__ void convert_wo_kernel(const float* __restrict__ Wo) {
    int i = blockIdx.x * 256 + threadIdx.x;
    float w = Wo[i];
    __half hh = __float2half_rn(w);
    g_WoH[i] = hh;
    g_WoL[i] = __float2half_rn(w - __half2float(hh));
}

// ---------------- mask build ------------------------------------------------
__global__ void build_mask_kernel(const int* __restrict__ graph) {
    int gwarp = (blockIdx.x * blockDim.x + threadIdx.x) >> 5;
    int lane  = threadIdx.x & 31;
    if (gwarp >= N_ * NW_) return;
    int n = gwarp >> 6;
    int w = gwarp & (NW_ - 1);
    int m = w * 32 + lane;
    bool bit = (graph[(size_t)n * N_ + m] != 0) || (m == n);
    unsigned word = __ballot_sync(0xffffffffu, bit);
    if (lane == 0) g_maskT[w * N_ + n] = word;
}

// ---------------- proj1: one head per blockIdx.y -----------------------------
__global__ void proj1_kernel(const float* __restrict__ x,
                             const float* __restrict__ Wh) {
    __shared__ float xs[64][65];
    __shared__ float ws[64][65];
    int t    = threadIdx.x;              // 256 threads
    int row0 = blockIdx.x * 64;
    int h    = blockIdx.y;
    for (int i = t; i < 64 * 64; i += 256) {
        int r = i >> 6, c = i & 63;
        xs[r][c] = x[(size_t)(row0 + r) * C_ + c];
        ws[r][c] = Wh[((size_t)h * D_ + r) * C_ + c];
    }
    __syncthreads();
    int d0 = (t & 15) * 4;
    int r0 = (t >> 4) * 4;
    int b     = row0 >> 11;
    int nbase = row0 & (N_ - 1);
    float acc[4][4] = {};
    #pragma unroll 8
    for (int c = 0; c < 64; ++c) {
        float xv[4], wv[4];
        #pragma unroll
        for (int i = 0; i < 4; ++i) { xv[i] = xs[r0 + i][c]; wv[i] = ws[d0 + i][c]; }
        #pragma unroll
        for (int i = 0; i < 4; ++i)
            #pragma unroll
            for (int j = 0; j < 4; ++j)
                acc[i][j] += xv[i] * wv[j];
    }
    #pragma unroll
    for (int i = 0; i < 4; ++i) {
        size_t base = (((size_t)(b * H_ + h) * N_) + nbase + r0 + i) * D_ + d0;
        split_store(g_hH, g_hL, base,     acc[i][0], acc[i][1]);
        split_store(g_hH, g_hL, base + 2, acc[i][2], acc[i][3]);
    }
}

// ---------------- reduce_h2: sum 4 head partials, split to f16 hi/lo --------
__global__ void reduce_h2_kernel() {
    int idx = blockIdx.x * 256 + threadIdx.x;    // float2 units
    int d2 = idx & 31;
    int n  = (idx >> 5) & (N_ - 1);
    int b  = idx >> 16;
    float2 s = make_float2(0.f, 0.f);
    #pragma unroll
    for (int h = 0; h < H_; ++h) {
        float2 v = *(const float2*)&g_h2p[(((size_t)(b * H_ + h) * N_) + n) * D_ + d2 * 2];
        s.x += v.x; s.y += v.y;
    }
    split_store(g_h2H, g_h2L, ((size_t)(b * N_ + n)) * D_ + d2 * 2, s.x, s.y);
}

// ================= HMMA flash attention, 4 warps / 64 rows, 4 blocks/SM =====
// KV tile = 64 cols, 3-deep cp.async ring (KH only).
// S = Qh*Kh + Ql*Kh (Ql frags loaded transiently per kf), P f16, O = P*Vh.
// LAYER 1 epilogue: fused per-head proj2 partial via 3-term MMA.
#define SQ 72                          // smem row stride in halves
#define NT 32                          // KV tiles
#define SM_QH 0
#define SM_QL 4608
#define SM_K  9216                     // ring starts after QH/QL
#define KBUF_HALVES 4608               // KH[64][72]
#define SMEM_ATT ((9216 + 3 * KBUF_HALVES) * 2)   // 46080 bytes

template <int LAYER>
__global__ void __launch_bounds__(128, 4)
attn_mma(const float* __restrict__ bias,
         const float* __restrict__ gamma,
         const float* __restrict__ beta,
         float* __restrict__ outp) {
    extern __shared__ __half smh[];
    const int t    = threadIdx.x;
    const int wid  = t >> 5;            // 0..3
    const int lane = t & 31;
    const int g    = lane >> 2;
    const int tg   = lane & 3;
    const int wr0  = wid << 4;
    const int bh   = blockIdx.x;
    const int row0 = blockIdx.y << 6;   // 64 query rows per block
    const __half* hH = (LAYER == 1 ? g_hH : g_h2H) + (size_t)bh * (N_ * D_);
    const __half* hL = (LAYER == 1 ? g_hL : g_h2L) + (size_t)bh * (N_ * D_);
    const uint32_t sbase = smem_u32(smh);

    // ---- stage Q hi + lo (64 rows) via plain loads ----
    {
        const uint4* sH = (const uint4*)(hH + (size_t)row0 * D_);
        const uint4* sL = (const uint4*)(hL + (size_t)row0 * D_);
        #pragma unroll
        for (int i = 0; i < 4; ++i) {
            int idx = t + (i << 7);            // 0..511
            int r = idx >> 3, c8 = (idx & 7) << 3;
            *(uint4*)&smh[SM_QH + r * SQ + c8] = sH[idx];
            *(uint4*)&smh[SM_QL + r * SQ + c8] = sL[idx];
        }
    }
    // ---- prefetch K tiles 0,1 (hi only) into ring buffers 0,1 ----
    #pragma unroll
    for (int pt = 0; pt < 2; ++pt) {
        const uint4* sH = (const uint4*)(hH + (size_t)pt * (64 * D_));
        uint32_t kb = sbase + (uint32_t)(SM_K + pt * KBUF_HALVES) * 2;
        #pragma unroll
        for (int i = 0; i < 4; ++i) {
            int idx = t + (i << 7);
            int r = idx >> 3, c8 = (idx & 7) << 3;
            cp16(kb + (((uint32_t)(r * SQ + c8)) << 1), sH + idx);
        }
        asm volatile("cp.async.commit_group;" ::: "memory");
    }
    __syncthreads();

    // ---- preload Q-hi A-frags; Q-lo loaded transiently in the loop ----
    const int arow  = wr0 + (lane & 15);
    const int acolb = (lane >> 4) << 3;
    uint32_t qh[4][4];
    #pragma unroll
    for (int kf = 0; kf < 4; ++kf)
        ldsm4(qh[kf], sbase + ((uint32_t)(SM_QH + arow * SQ + (kf << 4) + acolb) << 1));

    float oacc[8][4];
    #pragma unroll
    for (int i = 0; i < 8; ++i)
        #pragma unroll
        for (int j = 0; j < 4; ++j) oacc[i][j] = 0.f;
    float rs0 = 0.f, rs1 = 0.f, mr0 = -1e30f, mr1 = -1e30f;
    const int grow0 = row0 + wr0 + g;

    int buf = 0;
    #pragma unroll 1
    for (int tile = 0; tile < NT; ++tile) {
        asm volatile("cp.async.wait_group 1;" ::: "memory");
        __syncthreads();
        // ---- prefetch tile+2 into ring slot ----
        {
            int pt = tile + 2;
            if (pt < NT) {
                int pb = buf + 2; if (pb >= 3) pb -= 3;
                const uint4* sH = (const uint4*)(hH + (size_t)pt * (64 * D_));
                uint32_t kb = sbase + (uint32_t)(SM_K + pb * KBUF_HALVES) * 2;
                #pragma unroll
                for (int i = 0; i < 4; ++i) {
                    int idx = t + (i << 7);
                    int r = idx >> 3, c8 = (idx & 7) << 3;
                    cp16(kb + (((uint32_t)(r * SQ + c8)) << 1), sH + idx);
                }
            }
            asm volatile("cp.async.commit_group;" ::: "memory");   // empty group ok
        }
        unsigned mw0[2], mw1[2];
        #pragma unroll
        for (int w = 0; w < 2; ++w) {
            mw0[w] = g_maskT[(size_t)((tile << 1) + w) * N_ + grow0];
            mw1[w] = g_maskT[(size_t)((tile << 1) + w) * N_ + grow0 + 8];
        }

        const uint32_t kbH = sbase + (uint32_t)(SM_K + buf * KBUF_HALVES) * 2;

        // ---- GEMM-S: sacc = Qh*Kh + Ql*Kh (Ql transient; bfr chunked) ----
        float sacc[8][4];
        #pragma unroll
        for (int i = 0; i < 8; ++i)
            #pragma unroll
            for (int j = 0; j < 4; ++j) sacc[i][j] = 0.f;
        {
            const int brow = ((lane >> 4) << 3) + (lane & 7);
            const int bcol = ((lane >> 3) & 1) << 3;
            #pragma unroll
            for (int kf = 0; kf < 4; ++kf) {
                uint32_t qlt[4];
                ldsm4(qlt, sbase + ((uint32_t)(SM_QL + arow * SQ + (kf << 4) + acolb) << 1));
                #pragma unroll
                for (int hs = 0; hs < 2; ++hs) {
                    uint32_t bfr[4][2];
                    #pragma unroll
                    for (int j = 0; j < 2; ++j) {
                        uint32_t r4[4];
                        int jj = hs * 2 + j;
                        ldsm4(r4, kbH + ((uint32_t)(((jj << 4) + brow) * SQ
                                                    + (kf << 4) + bcol) << 1));
                        bfr[2*j][0] = r4[0]; bfr[2*j][1] = r4[1];
                        bfr[2*j+1][0] = r4[2]; bfr[2*j+1][1] = r4[3];
                    }
                    #pragma unroll
                    for (int nf = 0; nf < 4; ++nf) mma16816(sacc[hs*4+nf], qh[kf], bfr[nf]);
                    #pragma unroll
                    for (int nf = 0; nf < 4; ++nf) mma16816(sacc[hs*4+nf], qlt, bfr[nf]);
                }
            }
        }

        // ---- masked online softmax; P -> A-frags in registers ----
        float m0 = -1e30f, m1 = -1e30f;
        #pragma unroll
        for (int nf = 0; nf < 8; ++nf) {
            unsigned w0 = mw0[nf >> 2], w1 = mw1[nf >> 2];
            int bb = ((nf & 3) << 3) + (tg << 1);
            m0 = fmaxf(m0, ((w0 >> bb) & 1u)       ? sacc[nf][0] : -1e30f);
            m0 = fmaxf(m0, ((w0 >> (bb + 1)) & 1u) ? sacc[nf][1] : -1e30f);
            m1 = fmaxf(m1, ((w1 >> bb) & 1u)       ? sacc[nf][2] : -1e30f);
            m1 = fmaxf(m1, ((w1 >> (bb + 1)) & 1u) ? sacc[nf][3] : -1e30f);
        }
        m0 = fmaxf(m0, __shfl_xor_sync(0xffffffffu, m0, 1));
        m0 = fmaxf(m0, __shfl_xor_sync(0xffffffffu, m0, 2));
        m1 = fmaxf(m1, __shfl_xor_sync(0xffffffffu, m1, 1));
        m1 = fmaxf(m1, __shfl_xor_sync(0xffffffffu, m1, 2));
        float mn0 = fmaxf(mr0, m0), mn1 = fmaxf(mr1, m1);
        float al0 = ex2((mr0 - mn0) * LOG2E), al1 = ex2((mr1 - mn1) * LOG2E);
        mr0 = mn0; mr1 = mn1;
        rs0 *= al0; rs1 *= al1;
        #pragma unroll
        for (int nf = 0; nf < 8; ++nf) {
            oacc[nf][0] *= al0; oacc[nf][1] *= al0;
            oacc[nf][2] *= al1; oacc[nf][3] *= al1;
        }
        const float mL0 = mn0 * LOG2E, mL1 = mn1 * LOG2E;
        uint32_t pa[4][4];
        #pragma unroll
        for (int k2 = 0; k2 < 4; ++k2) {
            int nfA = k2 << 1, nfB = nfA + 1;
            unsigned wA0 = mw0[nfA >> 2], wA1 = mw1[nfA >> 2];
            unsigned wB0 = mw0[nfB >> 2], wB1 = mw1[nfB >> 2];
            int bbA = ((nfA & 3) << 3) + (tg << 1);
            int bbB = ((nfB & 3) << 3) + (tg << 1);
            float p00 = ((wA0 >> bbA) & 1u)     ? ex2(fmaf(sacc[nfA][0], LOG2E, -mL0)) : 0.f;
            float p01 = ((wA0 >> (bbA+1)) & 1u) ? ex2(fmaf(sacc[nfA][1], LOG2E, -mL0)) : 0.f;
            float p02 = ((wA1 >> bbA) & 1u)     ? ex2(fmaf(sacc[nfA][2], LOG2E, -mL1)) : 0.f;
            float p03 = ((wA1 >> (bbA+1)) & 1u) ? ex2(fmaf(sacc[nfA][3], LOG2E, -mL1)) : 0.f;
            float p10 = ((wB0 >> bbB) & 1u)     ? ex2(fmaf(sacc[nfB][0], LOG2E, -mL0)) : 0.f;
            float p11 = ((wB0 >> (bbB+1)) & 1u) ? ex2(fmaf(sacc[nfB][1], LOG2E, -mL0)) : 0.f;
            float p12 = ((wB1 >> bbB) & 1u)     ? ex2(fmaf(sacc[nfB][2], LOG2E, -mL1)) : 0.f;
            float p13 = ((wB1 >> (bbB+1)) & 1u) ? ex2(fmaf(sacc[nfB][3], LOG2E, -mL1)) : 0.f;
            __half2 h0 = __floats2half2_rn(p00, p01);
            __half2 h1 = __floats2half2_rn(p02, p03);
            __half2 h2 = __floats2half2_rn(p10, p11);
            __half2 h3 = __floats2half2_rn(p12, p13);
            pa[k2][0] = *(uint32_t*)&h0; pa[k2][1] = *(uint32_t*)&h1;
            pa[k2][2] = *(uint32_t*)&h2; pa[k2][3] = *(uint32_t*)&h3;
            float2 f0 = __half22float2(h0), f2 = __half22float2(h2);
            float2 f1 = __half22float2(h1), f3 = __half22float2(h3);
            rs0 += (f0.x + f0.y) + (f2.x + f2.y);
            rs1 += (f1.x + f1.y) + (f3.x + f3.y);
        }

        // ---- GEMM-A: O += P * Vh (bv chunked) ----
        {
            const int brow  = (((lane >> 3) & 1) << 3) + (lane & 7);
            const int bcolb = (lane >> 4) << 3;
            #pragma unroll
            for (int kf = 0; kf < 4; ++kf) {
                #pragma unroll
                for (int hs = 0; hs < 2; ++hs) {
                    uint32_t bv[4][2];
                    #pragma unroll
                    for (int j = 0; j < 2; ++j) {
                        uint32_t r4[4];
                        int jj = hs * 2 + j;
                        ldsm4t(r4, kbH + ((uint32_t)(((kf << 4) + brow) * SQ
                                                     + (jj << 4) + bcolb) << 1));
                        bv[2*j][0] = r4[0]; bv[2*j][1] = r4[1];
                        bv[2*j+1][0] = r4[2]; bv[2*j+1][1] = r4[3];
                    }
                    #pragma unroll
                    for (int nf = 0; nf < 4; ++nf) mma16816(oacc[hs*4+nf], pa[kf], bv[nf]);
                }
            }
        }
        if (++buf == 3) buf = 0;
    }

    // ---- finalize: rowsum quad-reduce ----
    rs0 += __shfl_xor_sync(0xffffffffu, rs0, 1);
    rs0 += __shfl_xor_sync(0xffffffffu, rs0, 2);
    rs1 += __shfl_xor_sync(0xffffffffu, rs1, 1);
    rs1 += __shfl_xor_sync(0xffffffffu, rs1, 2);
    float inv0 = 1.f / rs0, inv1 = 1.f / rs1;

    if (LAYER == 1) {
        // ---- fused proj2 slice: h2_partial = lrelu(z_slice) @ Wo_slice^T ----
        const int h = bh & (H_ - 1);
        // z in place of oacc
        #pragma unroll
        for (int nf = 0; nf < 8; ++nf) {
            int c = (nf << 3) + (tg << 1);
            float b0v = bias[h * D_ + c], b1v = bias[h * D_ + c + 1];
            oacc[nf][0] = lrelu(fmaf(oacc[nf][0], inv0, b0v));
            oacc[nf][1] = lrelu(fmaf(oacc[nf][1], inv0, b1v));
            oacc[nf][2] = lrelu(fmaf(oacc[nf][2], inv1, b0v));
            oacc[nf][3] = lrelu(fmaf(oacc[nf][3], inv1, b1v));
        }
        uint32_t zh[4][4], zl[4][4];
        #pragma unroll
        for (int kf = 0; kf < 4; ++kf) {
            int nfA = kf << 1, nfB = nfA + 1;
            __half2 hA0 = __floats2half2_rn(oacc[nfA][0], oacc[nfA][1]);
            __half2 hA1 = __floats2half2_rn(oacc[nfA][2], oacc[nfA][3]);
            __half2 hB0 = __floats2half2_rn(oacc[nfB][0], oacc[nfB][1]);
            __half2 hB1 = __floats2half2_rn(oacc[nfB][2], oacc[nfB][3]);
            float2 fA0 = __half22float2(hA0), fA1 = __half22float2(hA1);
            float2 fB0 = __half22float2(hB0), fB1 = __half22float2(hB1);
            __half2 lA0 = __floats2half2_rn(oacc[nfA][0] - fA0.x, oacc[nfA][1] - fA0.y);
            __half2 lA1 = __floats2half2_rn(oacc[nfA][2] - fA1.x, oacc[nfA][3] - fA1.y);
            __half2 lB0 = __floats2half2_rn(oacc[nfB][0] - fB0.x, oacc[nfB][1] - fB0.y);
            __half2 lB1 = __floats2half2_rn(oacc[nfB][2] - fB1.x, oacc[nfB][3] - fB1.y);
            zh[kf][0] = *(uint32_t*)&hA0; zh[kf][1] = *(uint32_t*)&hA1;
            zh[kf][2] = *(uint32_t*)&hB0; zh[kf][3] = *(uint32_t*)&hB1;
            zl[kf][0] = *(uint32_t*)&lA0; zl[kf][1] = *(uint32_t*)&lA1;
            zl[kf][2] = *(uint32_t*)&lB0; zl[kf][3] = *(uint32_t*)&lB1;
        }
        // stage Wo head slice (hi, lo) into dead ring smem
        __syncthreads();
        #pragma unroll
        for (int i = 0; i < 4; ++i) {
            int idx = t + (i << 7);
            int r = idx >> 3, c8 = (idx & 7) << 3;
            *(uint4*)&smh[SM_K + r * SQ + c8] =
                *(const uint4*)(g_WoH + (size_t)r * HD_ + h * D_ + c8);
            *(uint4*)&smh[SM_K + KBUF_HALVES + r * SQ + c8] =
                *(const uint4*)(g_WoL + (size_t)r * HD_ + h * D_ + c8);
        }
        __syncthreads();
        // 3-term MMA: zh*WoH + zl*WoH + zh*WoL (reuse oacc as output)
        float o2[8][4];
        #pragma unroll
        for (int i = 0; i < 8; ++i)
            #pragma unroll
            for (int j = 0; j < 4; ++j) o2[i][j] = 0.f;
        {
            const int brow = ((lane >> 4) << 3) + (lane & 7);
            const int bcol = ((lane >> 3) & 1) << 3;
            const uint32_t wbH = sbase + (uint32_t)SM_K * 2;
            const uint32_t wbL = wbH + ((uint32_t)KBUF_HALVES << 1);
            #pragma unroll
            for (int kf = 0; kf < 4; ++kf) {
                #pragma unroll
                for (int hs = 0; hs < 2; ++hs) {
                    uint32_t bfr[4][2];
                    #pragma unroll
                    for (int j = 0; j < 2; ++j) {
                        uint32_t r4[4];
                        int jj = hs * 2 + j;
                        ldsm4(r4, wbH + ((uint32_t)(((jj << 4) + brow) * SQ
                                                    + (kf << 4) + bcol) << 1));
                        bfr[2*j][0] = r4[0]; bfr[2*j][1] = r4[1];
                        bfr[2*j+1][0] = r4[2]; bfr[2*j+1][1] = r4[3];
                    }
                    #pragma unroll
                    for (int nf = 0; nf < 4; ++nf) mma16816(o2[hs*4+nf], zh[kf], bfr[nf]);
                    #pragma unroll
                    for (int nf = 0; nf < 4; ++nf) mma16816(o2[hs*4+nf], zl[kf], bfr[nf]);
                    #pragma unroll
                    for (int j = 0; j < 2; ++j) {
                        uint32_t r4[4];
                        int jj = hs * 2 + j;
                        ldsm4(r4, wbL + ((uint32_t)(((jj << 4) + brow) * SQ
                                                    + (kf << 4) + bcol) << 1));
                        bfr[2*j][0] = r4[0]; bfr[2*j][1] = r4[1];
                        bfr[2*j+1][0] = r4[2]; bfr[2*j+1][1] = r4[3];
                    }
                    #pragma unroll
                    for (int nf = 0; nf < 4; ++nf) mma16816(o2[hs*4+nf], zh[kf], bfr[nf]);
                }
            }
        }
        size_t rb = ((size_t)bh * N_ + grow0) * D_;
        #pragma unroll
        for (int nf = 0; nf < 8; ++nf) {
            int d = (nf << 3) + (tg << 1);
            *(float2*)&g_h2p[rb + d]           = make_float2(o2[nf][0], o2[nf][1]);
            *(float2*)&g_h2p[rb + 8 * D_ + d]  = make_float2(o2[nf][2], o2[nf][3]);
        }
    } else {
        float v0[16], v1[16];
        float s0 = 0.f, s1 = 0.f;
        #pragma unroll
        for (int nf = 0; nf < 8; ++nf) {
            int c = (nf << 3) + (tg << 1);
            float b0v = bias[c], b1v = bias[c + 1];
            float a;
            a = lrelu(fmaf(oacc[nf][0], inv0, b0v)); v0[2*nf]   = a; s0 += a;
            a = lrelu(fmaf(oacc[nf][1], inv0, b1v)); v0[2*nf+1] = a; s0 += a;
            a = lrelu(fmaf(oacc[nf][2], inv1, b0v)); v1[2*nf]   = a; s1 += a;
            a = lrelu(fmaf(oacc[nf][3], inv1, b1v)); v1[2*nf+1] = a; s1 += a;
        }
        s0 += __shfl_xor_sync(0xffffffffu, s0, 1);
        s0 += __shfl_xor_sync(0xffffffffu, s0, 2);
        s1 += __shfl_xor_sync(0xffffffffu, s1, 1);
        s1 += __shfl_xor_sync(0xffffffffu, s1, 2);
        float mu0 = s0 * (1.f / 64.f), mu1 = s1 * (1.f / 64.f);
        float q0 = 0.f, q1 = 0.f;
        #pragma unroll
        for (int i = 0; i < 16; ++i) {
            float u0 = v0[i] - mu0; q0 += u0 * u0;
            float u1 = v1[i] - mu1; q1 += u1 * u1;
        }
        q0 += __shfl_xor_sync(0xffffffffu, q0, 1);
        q0 += __shfl_xor_sync(0xffffffffu, q0, 2);
        q1 += __shfl_xor_sync(0xffffffffu, q1, 1);
        q1 += __shfl_xor_sync(0xffffffffu, q1, 2);
        float rstd0 = rsqrtf(q0 * (1.f / 64.f) + 1e-5f);
        float rstd1 = rsqrtf(q1 * (1.f / 64.f) + 1e-5f);
        float* od0 = outp + ((size_t)bh * N_ + grow0) * D_;
        float* od1 = od0 + 8 * D_;
        #pragma unroll
        for (int nf = 0; nf < 8; ++nf) {
            int c = (nf << 3) + (tg << 1);
            float ga0 = gamma[c], ga1 = gamma[c + 1];
            float be0 = beta[c],  be1 = beta[c + 1];
            float2 w0, w1;
            w0.x = (v0[2*nf]   - mu0) * rstd0 * ga0 + be0;
            w0.y = (v0[2*nf+1] - mu0) * rstd0 * ga1 + be1;
            w1.x = (v1[2*nf]   - mu1) * rstd1 * ga0 + be0;
            w1.y = (v1[2*nf+1] - mu1) * rstd1 * ga1 + be1;
            *(float2*)&od0[c] = w0;
            *(float2*)&od1[c] = w1;
        }
    }
}

// ---------------- launch -----------------------------------------------------
extern "C" void kernel_launch(void* const* d_in, const int* in_sizes, int n_in,
                              void* d_out, int out_size) {
    const float* x     = (const float*)d_in[0];
    const int*   graph = (const int*)  d_in[1];
    const float* Wh    = (const float*)d_in[2];
    const float* bh    = (const float*)d_in[3];
    const float* Wo    = (const float*)d_in[4];
    const float* bo    = (const float*)d_in[5];
    const float* gamma = (const float*)d_in[6];
    const float* beta  = (const float*)d_in[7];
    float* out = (float*)d_out;

    cudaFuncSetAttribute(attn_mma<1>, cudaFuncAttributeMaxDynamicSharedMemorySize, SMEM_ATT);
    cudaFuncSetAttribute(attn_mma<2>, cudaFuncAttributeMaxDynamicSharedMemorySize, SMEM_ATT);

    convert_wo_kernel<<<64, 256>>>(Wo);
    build_mask_kernel<<<(N_ * NW_) / 8, 256>>>(graph);
    proj1_kernel<<<dim3(B_ * N_ / 64, H_), 256>>>(x, Wh);
    attn_mma<1><<<dim3(B_ * H_, N_ / 64), 128, SMEM_ATT>>>(bh, nullptr, nullptr, nullptr);
    reduce_h2_kernel<<<(B_ * N_ * 32) / 256, 256>>>();
    attn_mma<2><<<dim3(B_, N_ / 64), 128, SMEM_ATT>>>(bo, gamma, beta, out);
}

// round 15
// speedup vs baseline: 1.3509x; 1.1748x over previous
#include <cuda_runtime.h>
#include <cuda_fp16.h>
#include <cstdint>

// Problem shape (fixed for this registry entry)
#define B_  8
#define N_  2048
#define C_  64
#define H_  4
#define D_  64
#define HD_ 256          // H*D
#define NW_ (N_/32)      // mask words per row = 64
#define LOG2E 1.4426950408889634f

// ---------------- scratch (device globals: no allocation allowed) -----------
__device__ __half  g_hH [B_*H_*N_*D_];    // layer1 features, f16 hi
__device__ __half  g_hL [B_*H_*N_*D_];    // layer1 features, f16 lo (residual)
__device__ __half  g_h2H[B_*N_*D_];       // layer2 features hi
__device__ __half  g_h2L[B_*N_*D_];       // layer2 features lo
__device__ float   g_h2p[B_*H_*N_*D_];    // per-head partial h2 (deterministic)
__device__ __half  g_WoH[D_*HD_];         // Wo f16 hi
__device__ __half  g_WoL[D_*HD_];         // Wo f16 lo
__device__ unsigned g_maskT[NW_*N_];      // transposed bitmask [w][n]

__device__ __forceinline__ float ex2(float x) {
    float y;
    asm("ex2.approx.f32 %0, %1;" : "=f"(y) : "f"(x));
    return y;
}
__device__ __forceinline__ uint32_t smem_u32(const void* p) {
    uint32_t a;
    asm("{ .reg .u64 t; cvta.to.shared.u64 t, %1; cvt.u32.u64 %0, t; }" : "=r"(a) : "l"(p));
    return a;
}
__device__ __forceinline__ void cp16(uint32_t saddr, const void* g) {
    asm volatile("cp.async.ca.shared.global [%0], [%1], 16;"
                 :: "r"(saddr), "l"(__cvta_generic_to_global(g)));
}
__device__ __forceinline__ void ldsm4(uint32_t r[4], uint32_t addr) {
    asm volatile("ldmatrix.sync.aligned.m8n8.x4.shared.b16 {%0,%1,%2,%3}, [%4];"
                 : "=r"(r[0]), "=r"(r[1]), "=r"(r[2]), "=r"(r[3]) : "r"(addr));
}
__device__ __forceinline__ void ldsm4t(uint32_t r[4], uint32_t addr) {
    asm volatile("ldmatrix.sync.aligned.m8n8.x4.trans.shared.b16 {%0,%1,%2,%3}, [%4];"
                 : "=r"(r[0]), "=r"(r[1]), "=r"(r[2]), "=r"(r[3]) : "r"(addr));
}
__device__ __forceinline__ void mma16816(float d[4], const uint32_t a[4], const uint32_t b[2]) {
    asm volatile("mma.sync.aligned.m16n8k16.row.col.f32.f16.f16.f32 "
                 "{%0,%1,%2,%3}, {%4,%5,%6,%7}, {%8,%9}, {%0,%1,%2,%3};"
                 : "+f"(d[0]), "+f"(d[1]), "+f"(d[2]), "+f"(d[3])
                 : "r"(a[0]), "r"(a[1]), "r"(a[2]), "r"(a[3]), "r"(b[0]), "r"(b[1]));
}
__device__ __forceinline__ float lrelu(float a) { return a > 0.f ? a : 0.2f * a; }

__device__ __forceinline__ void split_store(__half* dH, __half* dL, size_t idx,
                                            float v0, float v1) {
    __half h0 = __float2half_rn(v0), h1 = __float2half_rn(v1);
    __half l0 = __float2half_rn(v0 - __half2float(h0));
    __half l1 = __float2half_rn(v1 - __half2float(h1));
    *(__half2*)&dH[idx] = __halves2half2(h0, h1);
    *(__half2*)&dL[idx] = __halves2half2(l0, l1);
}

// ---------------- one-time Wo f16 hi/lo split --------------------------------
__global__ void convert_wo_kernel(const float* __restrict__ Wo) {
    int i = blockIdx.x * 256 + threadIdx.x;
    float w = Wo[i];
    __half hh = __float2half_rn(w);
    g_WoH[i] = hh;
    g_WoL[i] = __float2half_rn(w - __half2float(hh));
}

// ---------------- mask build ------------------------------------------------
__global__ void build_mask_kernel(const int* __restrict__ graph) {
    int gwarp = (blockIdx.x * blockDim.x + threadIdx.x) >> 5;
    int lane  = threadIdx.x & 31;
    if (gwarp >= N_ * NW_) return;
    int n = gwarp >> 6;
    int w = gwarp & (NW_ - 1);
    int m = w * 32 + lane;
    bool bit = (graph[(size_t)n * N_ + m] != 0) || (m == n);
    unsigned word = __ballot_sync(0xffffffffu, bit);
    if (lane == 0) g_maskT[w * N_ + n] = word;
}

// ---------------- proj1: one head per blockIdx.y -----------------------------
__global__ void proj1_kernel(const float* __restrict__ x,
                             const float* __restrict__ Wh) {
    __shared__ float xs[64][65];
    __shared__ float ws[64][65];
    int t    = threadIdx.x;              // 256 threads
    int row0 = blockIdx.x * 64;
    int h    = blockIdx.y;
    for (int i = t; i < 64 * 64; i += 256) {
        int r = i >> 6, c = i & 63;
        xs[r][c] = x[(size_t)(row0 + r) * C_ + c];
        ws[r][c] = Wh[((size_t)h * D_ + r) * C_ + c];
    }
    __syncthreads();
    int d0 = (t & 15) * 4;
    int r0 = (t >> 4) * 4;
    int b     = row0 >> 11;
    int nbase = row0 & (N_ - 1);
    float acc[4][4] = {};
    #pragma unroll 8
    for (int c = 0; c < 64; ++c) {
        float xv[4], wv[4];
        #pragma unroll
        for (int i = 0; i < 4; ++i) { xv[i] = xs[r0 + i][c]; wv[i] = ws[d0 + i][c]; }
        #pragma unroll
        for (int i = 0; i < 4; ++i)
            #pragma unroll
            for (int j = 0; j < 4; ++j)
                acc[i][j] += xv[i] * wv[j];
    }
    #pragma unroll
    for (int i = 0; i < 4; ++i) {
        size_t base = (((size_t)(b * H_ + h) * N_) + nbase + r0 + i) * D_ + d0;
        split_store(g_hH, g_hL, base,     acc[i][0], acc[i][1]);
        split_store(g_hH, g_hL, base + 2, acc[i][2], acc[i][3]);
    }
}

// ---------------- reduce_h2: sum 4 head partials, split to f16 hi/lo --------
__global__ void reduce_h2_kernel() {
    int idx = blockIdx.x * 256 + threadIdx.x;    // float2 units
    int d2 = idx & 31;
    int n  = (idx >> 5) & (N_ - 1);
    int b  = idx >> 16;
    float2 s = make_float2(0.f, 0.f);
    #pragma unroll
    for (int h = 0; h < H_; ++h) {
        float2 v = *(const float2*)&g_h2p[(((size_t)(b * H_ + h) * N_) + n) * D_ + d2 * 2];
        s.x += v.x; s.y += v.y;
    }
    split_store(g_h2H, g_h2L, ((size_t)(b * N_ + n)) * D_ + d2 * 2, s.x, s.y);
}

// ================= HMMA flash attention, NW warps / NW*16 rows ==============
// KV tile = 64 cols, 3-deep cp.async ring (KH only).
// S = Qh*Kh + Ql*Kh (Ql transient), unmasked tile max (f16-safe upper bound),
// mask applied exactly at P. P f16, O = P*Vh.
// LAYER 1 (NW=4): fused per-head proj2 partial. LAYER 2 (NW=2): LN epilogue.
#define SQ 72                          // smem row stride in halves
#define NT 32                          // KV tiles
#define KBUF_HALVES 4608               // KH[64][72]
#define SMEM_ATT(NWv) ((2 * ((NWv)*16*SQ) + 3 * KBUF_HALVES) * 2)

template <int LAYER, int NW>
__global__ void __launch_bounds__(NW * 32, 4)
attn_mma(const float* __restrict__ bias,
         const float* __restrict__ gamma,
         const float* __restrict__ beta,
         float* __restrict__ outp) {
    constexpr int ROWS   = NW * 16;
    constexpr int NTHR   = NW * 32;
    constexpr int SM_QH  = 0;
    constexpr int SM_QL  = ROWS * SQ;
    constexpr int SM_K   = 2 * ROWS * SQ;
    constexpr int KIT    = 512 / NTHR;     // uint4 iterations for a 64-row K tile

    extern __shared__ __half smh[];
    const int t    = threadIdx.x;
    const int wid  = t >> 5;
    const int lane = t & 31;
    const int g    = lane >> 2;
    const int tg   = lane & 3;
    const int wr0  = wid << 4;
    const int bh   = blockIdx.x;
    const int row0 = blockIdx.y * ROWS;
    const __half* hH = (LAYER == 1 ? g_hH : g_h2H) + (size_t)bh * (N_ * D_);
    const __half* hL = (LAYER == 1 ? g_hL : g_h2L) + (size_t)bh * (N_ * D_);
    const uint32_t sbase = smem_u32(smh);

    // ---- stage Q hi + lo (ROWS rows) ----
    {
        const uint4* sH = (const uint4*)(hH + (size_t)row0 * D_);
        const uint4* sL = (const uint4*)(hL + (size_t)row0 * D_);
        #pragma unroll
        for (int i = 0; i < 4; ++i) {
            int idx = t + i * NTHR;            // 0..ROWS*8-1
            int r = idx >> 3, c8 = (idx & 7) << 3;
            *(uint4*)&smh[SM_QH + r * SQ + c8] = sH[idx];
            *(uint4*)&smh[SM_QL + r * SQ + c8] = sL[idx];
        }
    }
    // ---- prefetch K tiles 0,1 (hi only) into ring buffers 0,1 ----
    #pragma unroll
    for (int pt = 0; pt < 2; ++pt) {
        const uint4* sH = (const uint4*)(hH + (size_t)pt * (64 * D_));
        uint32_t kb = sbase + (uint32_t)(SM_K + pt * KBUF_HALVES) * 2;
        #pragma unroll
        for (int i = 0; i < KIT; ++i) {
            int idx = t + i * NTHR;
            int r = idx >> 3, c8 = (idx & 7) << 3;
            cp16(kb + (((uint32_t)(r * SQ + c8)) << 1), sH + idx);
        }
        asm volatile("cp.async.commit_group;" ::: "memory");
    }
    __syncthreads();

    // ---- preload Q-hi A-frags; Q-lo transient ----
    const int arow  = wr0 + (lane & 15);
    const int acolb = (lane >> 4) << 3;
    uint32_t qh[4][4];
    #pragma unroll
    for (int kf = 0; kf < 4; ++kf)
        ldsm4(qh[kf], sbase + ((uint32_t)(SM_QH + arow * SQ + (kf << 4) + acolb) << 1));

    float oacc[8][4];
    #pragma unroll
    for (int i = 0; i < 8; ++i)
        #pragma unroll
        for (int j = 0; j < 4; ++j) oacc[i][j] = 0.f;
    float rs0 = 0.f, rs1 = 0.f, mr0 = -1e30f, mr1 = -1e30f;
    const int grow0 = row0 + wr0 + g;

    int buf = 0;
    #pragma unroll 1
    for (int tile = 0; tile < NT; ++tile) {
        asm volatile("cp.async.wait_group 1;" ::: "memory");
        __syncthreads();
        // ---- prefetch tile+2 into ring slot ----
        {
            int pt = tile + 2;
            if (pt < NT) {
                int pb = buf + 2; if (pb >= 3) pb -= 3;
                const uint4* sH = (const uint4*)(hH + (size_t)pt * (64 * D_));
                uint32_t kb = sbase + (uint32_t)(SM_K + pb * KBUF_HALVES) * 2;
                #pragma unroll
                for (int i = 0; i < KIT; ++i) {
                    int idx = t + i * NTHR;
                    int r = idx >> 3, c8 = (idx & 7) << 3;
                    cp16(kb + (((uint32_t)(r * SQ + c8)) << 1), sH + idx);
                }
            }
            asm volatile("cp.async.commit_group;" ::: "memory");   // empty group ok
        }
        unsigned mw0[2], mw1[2];
        #pragma unroll
        for (int w = 0; w < 2; ++w) {
            mw0[w] = g_maskT[(size_t)((tile << 1) + w) * N_ + grow0];
            mw1[w] = g_maskT[(size_t)((tile << 1) + w) * N_ + grow0 + 8];
        }

        const uint32_t kbH = sbase + (uint32_t)(SM_K + buf * KBUF_HALVES) * 2;

        // ---- GEMM-S: sacc = Qh*Kh + Ql*Kh (Ql transient; bfr chunked) ----
        float sacc[8][4];
        #pragma unroll
        for (int i = 0; i < 8; ++i)
            #pragma unroll
            for (int j = 0; j < 4; ++j) sacc[i][j] = 0.f;
        {
            const int brow = ((lane >> 4) << 3) + (lane & 7);
            const int bcol = ((lane >> 3) & 1) << 3;
            #pragma unroll
            for (int kf = 0; kf < 4; ++kf) {
                uint32_t qlt[4];
                ldsm4(qlt, sbase + ((uint32_t)(SM_QL + arow * SQ + (kf << 4) + acolb) << 1));
                #pragma unroll
                for (int hs = 0; hs < 2; ++hs) {
                    uint32_t bfr[4][2];
                    #pragma unroll
                    for (int j = 0; j < 2; ++j) {
                        uint32_t r4[4];
                        int jj = hs * 2 + j;
                        ldsm4(r4, kbH + ((uint32_t)(((jj << 4) + brow) * SQ
                                                    + (kf << 4) + bcol) << 1));
                        bfr[2*j][0] = r4[0]; bfr[2*j][1] = r4[1];
                        bfr[2*j+1][0] = r4[2]; bfr[2*j+1][1] = r4[3];
                    }
                    #pragma unroll
                    for (int nf = 0; nf < 4; ++nf) mma16816(sacc[hs*4+nf], qh[kf], bfr[nf]);
                    #pragma unroll
                    for (int nf = 0; nf < 4; ++nf) mma16816(sacc[hs*4+nf], qlt, bfr[nf]);
                }
            }
        }

        // ---- softmax: UNMASKED tile max (upper bound, f16-safe) ----
        float m0 = -1e30f, m1 = -1e30f;
        #pragma unroll
        for (int nf = 0; nf < 8; ++nf) {
            m0 = fmaxf(m0, fmaxf(sacc[nf][0], sacc[nf][1]));
            m1 = fmaxf(m1, fmaxf(sacc[nf][2], sacc[nf][3]));
        }
        m0 = fmaxf(m0, __shfl_xor_sync(0xffffffffu, m0, 1));
        m0 = fmaxf(m0, __shfl_xor_sync(0xffffffffu, m0, 2));
        m1 = fmaxf(m1, __shfl_xor_sync(0xffffffffu, m1, 1));
        m1 = fmaxf(m1, __shfl_xor_sync(0xffffffffu, m1, 2));
        float mn0 = fmaxf(mr0, m0), mn1 = fmaxf(mr1, m1);
        float al0 = ex2((mr0 - mn0) * LOG2E), al1 = ex2((mr1 - mn1) * LOG2E);
        mr0 = mn0; mr1 = mn1;
        // skip rescale when running max unchanged for the whole warp
        if (__any_sync(0xffffffffu, (al0 != 1.f) || (al1 != 1.f))) {
            rs0 *= al0; rs1 *= al1;
            #pragma unroll
            for (int nf = 0; nf < 8; ++nf) {
                oacc[nf][0] *= al0; oacc[nf][1] *= al0;
                oacc[nf][2] *= al1; oacc[nf][3] *= al1;
            }
        }
        const float mL0 = mn0 * LOG2E, mL1 = mn1 * LOG2E;
        uint32_t pa[4][4];
        #pragma unroll
        for (int k2 = 0; k2 < 4; ++k2) {
            int nfA = k2 << 1, nfB = nfA + 1;
            unsigned wA0 = mw0[nfA >> 2], wA1 = mw1[nfA >> 2];
            unsigned wB0 = mw0[nfB >> 2], wB1 = mw1[nfB >> 2];
            int bbA = ((nfA & 3) << 3) + (tg << 1);
            int bbB = ((nfB & 3) << 3) + (tg << 1);
            float p00 = ((wA0 >> bbA) & 1u)     ? ex2(fmaf(sacc[nfA][0], LOG2E, -mL0)) : 0.f;
            float p01 = ((wA0 >> (bbA+1)) & 1u) ? ex2(fmaf(sacc[nfA][1], LOG2E, -mL0)) : 0.f;
            float p02 = ((wA1 >> bbA) & 1u)     ? ex2(fmaf(sacc[nfA][2], LOG2E, -mL1)) : 0.f;
            float p03 = ((wA1 >> (bbA+1)) & 1u) ? ex2(fmaf(sacc[nfA][3], LOG2E, -mL1)) : 0.f;
            float p10 = ((wB0 >> bbB) & 1u)     ? ex2(fmaf(sacc[nfB][0], LOG2E, -mL0)) : 0.f;
            float p11 = ((wB0 >> (bbB+1)) & 1u) ? ex2(fmaf(sacc[nfB][1], LOG2E, -mL0)) : 0.f;
            float p12 = ((wB1 >> bbB) & 1u)     ? ex2(fmaf(sacc[nfB][2], LOG2E, -mL1)) : 0.f;
            float p13 = ((wB1 >> (bbB+1)) & 1u) ? ex2(fmaf(sacc[nfB][3], LOG2E, -mL1)) : 0.f;
            __half2 h0 = __floats2half2_rn(p00, p01);
            __half2 h1 = __floats2half2_rn(p02, p03);
            __half2 h2 = __floats2half2_rn(p10, p11);
            __half2 h3 = __floats2half2_rn(p12, p13);
            pa[k2][0] = *(uint32_t*)&h0; pa[k2][1] = *(uint32_t*)&h1;
            pa[k2][2] = *(uint32_t*)&h2; pa[k2][3] = *(uint32_t*)&h3;
            float2 f0 = __half22float2(h0), f2 = __half22float2(h2);
            float2 f1 = __half22float2(h1), f3 = __half22float2(h3);
            rs0 += (f0.x + f0.y) + (f2.x + f2.y);
            rs1 += (f1.x + f1.y) + (f3.x + f3.y);
        }

        // ---- GEMM-A: O += P * Vh ----
        {
            const int brow  = (((lane >> 3) & 1) << 3) + (lane & 7);
            const int bcolb = (lane >> 4) << 3;
            #pragma unroll
            for (int kf = 0; kf < 4; ++kf) {
                #pragma unroll
                for (int hs = 0; hs < 2; ++hs) {
                    uint32_t bv[4][2];
                    #pragma unroll
                    for (int j = 0; j < 2; ++j) {
                        uint32_t r4[4];
                        int jj = hs * 2 + j;
                        ldsm4t(r4, kbH + ((uint32_t)(((kf << 4) + brow) * SQ
                                                     + (jj << 4) + bcolb) << 1));
                        bv[2*j][0] = r4[0]; bv[2*j][1] = r4[1];
                        bv[2*j+1][0] = r4[2]; bv[2*j+1][1] = r4[3];
                    }
                    #pragma unroll
                    for (int nf = 0; nf < 4; ++nf) mma16816(oacc[hs*4+nf], pa[kf], bv[nf]);
                }
            }
        }
        if (++buf == 3) buf = 0;
    }

    // ---- finalize: rowsum quad-reduce ----
    rs0 += __shfl_xor_sync(0xffffffffu, rs0, 1);
    rs0 += __shfl_xor_sync(0xffffffffu, rs0, 2);
    rs1 += __shfl_xor_sync(0xffffffffu, rs1, 1);
    rs1 += __shfl_xor_sync(0xffffffffu, rs1, 2);
    float inv0 = 1.f / rs0, inv1 = 1.f / rs1;

    if (LAYER == 1) {
        // ---- fused proj2 slice: h2_partial = lrelu(z_slice) @ Wo_slice^T ----
        const int h = bh & (H_ - 1);
        #pragma unroll
        for (int nf = 0; nf < 8; ++nf) {
            int c = (nf << 3) + (tg << 1);
            float b0v = bias[h * D_ + c], b1v = bias[h * D_ + c + 1];
            oacc[nf][0] = lrelu(fmaf(oacc[nf][0], inv0, b0v));
            oacc[nf][1] = lrelu(fmaf(oacc[nf][1], inv0, b1v));
            oacc[nf][2] = lrelu(fmaf(oacc[nf][2], inv1, b0v));
            oacc[nf][3] = lrelu(fmaf(oacc[nf][3], inv1, b1v));
        }
        uint32_t zh[4][4], zl[4][4];
        #pragma unroll
        for (int kf = 0; kf < 4; ++kf) {
            int nfA = kf << 1, nfB = nfA + 1;
            __half2 hA0 = __floats2half2_rn(oacc[nfA][0], oacc[nfA][1]);
            __half2 hA1 = __floats2half2_rn(oacc[nfA][2], oacc[nfA][3]);
            __half2 hB0 = __floats2half2_rn(oacc[nfB][0], oacc[nfB][1]);
            __half2 hB1 = __floats2half2_rn(oacc[nfB][2], oacc[nfB][3]);
            float2 fA0 = __half22float2(hA0), fA1 = __half22float2(hA1);
            float2 fB0 = __half22float2(hB0), fB1 = __half22float2(hB1);
            __half2 lA0 = __floats2half2_rn(oacc[nfA][0] - fA0.x, oacc[nfA][1] - fA0.y);
            __half2 lA1 = __floats2half2_rn(oacc[nfA][2] - fA1.x, oacc[nfA][3] - fA1.y);
            __half2 lB0 = __floats2half2_rn(oacc[nfB][0] - fB0.x, oacc[nfB][1] - fB0.y);
            __half2 lB1 = __floats2half2_rn(oacc[nfB][2] - fB1.x, oacc[nfB][3] - fB1.y);
            zh[kf][0] = *(uint32_t*)&hA0; zh[kf][1] = *(uint32_t*)&hA1;
            zh[kf][2] = *(uint32_t*)&hB0; zh[kf][3] = *(uint32_t*)&hB1;
            zl[kf][0] = *(uint32_t*)&lA0; zl[kf][1] = *(uint32_t*)&lA1;
            zl[kf][2] = *(uint32_t*)&lB0; zl[kf][3] = *(uint32_t*)&lB1;
        }
        __syncthreads();
        #pragma unroll
        for (int i = 0; i < 4; ++i) {
            int idx = t + i * NTHR;
            int r = idx >> 3, c8 = (idx & 7) << 3;
            *(uint4*)&smh[SM_K + r * SQ + c8] =
                *(const uint4*)(g_WoH + (size_t)r * HD_ + h * D_ + c8);
            *(uint4*)&smh[SM_K + KBUF_HALVES + r * SQ + c8] =
                *(const uint4*)(g_WoL + (size_t)r * HD_ + h * D_ + c8);
        }
        __syncthreads();
        float o2[8][4];
        #pragma unroll
        for (int i = 0; i < 8; ++i)
            #pragma unroll
            for (int j = 0; j < 4; ++j) o2[i][j] = 0.f;
        {
            const int brow = ((lane >> 4) << 3) + (lane & 7);
            const int bcol = ((lane >> 3) & 1) << 3;
            const uint32_t wbH = sbase + (uint32_t)SM_K * 2;
            const uint32_t wbL = wbH + ((uint32_t)KBUF_HALVES << 1);
            #pragma unroll
            for (int kf = 0; kf < 4; ++kf) {
                #pragma unroll
                for (int hs = 0; hs < 2; ++hs) {
                    uint32_t bfr[4][2];
                    #pragma unroll
                    for (int j = 0; j < 2; ++j) {
                        uint32_t r4[4];
                        int jj = hs * 2 + j;
                        ldsm4(r4, wbH + ((uint32_t)(((jj << 4) + brow) * SQ
                                                    + (kf << 4) + bcol) << 1));
                        bfr[2*j][0] = r4[0]; bfr[2*j][1] = r4[1];
                        bfr[2*j+1][0] = r4[2]; bfr[2*j+1][1] = r4[3];
                    }
                    #pragma unroll
                    for (int nf = 0; nf < 4; ++nf) mma16816(o2[hs*4+nf], zh[kf], bfr[nf]);
                    #pragma unroll
                    for (int nf = 0; nf < 4; ++nf) mma16816(o2[hs*4+nf], zl[kf], bfr[nf]);
                    #pragma unroll
                    for (int j = 0; j < 2; ++j) {
                        uint32_t r4[4];
                        int jj = hs * 2 + j;
                        ldsm4(r4, wbL + ((uint32_t)(((jj << 4) + brow) * SQ
                                                    + (kf << 4) + bcol) << 1));
                        bfr[2*j][0] = r4[0]; bfr[2*j][1] = r4[1];
                        bfr[2*j+1][0] = r4[2]; bfr[2*j+1][1] = r4[3];
                    }
                    #pragma unroll
                    for (int nf = 0; nf < 4; ++nf) mma16816(o2[hs*4+nf], zh[kf], bfr[nf]);
                }
            }
        }
        size_t rb = ((size_t)bh * N_ + grow0) * D_;
        #pragma unroll
        for (int nf = 0; nf < 8; ++nf) {
            int d = (nf << 3) + (tg << 1);
            *(float2*)&g_h2p[rb + d]           = make_float2(o2[nf][0], o2[nf][1]);
            *(float2*)&g_h2p[rb + 8 * D_ + d]  = make_float2(o2[nf][2], o2[nf][3]);
        }
    } else {
        float v0[16], v1[16];
        float s0 = 0.f, s1 = 0.f;
        #pragma unroll
        for (int nf = 0; nf < 8; ++nf) {
            int c = (nf << 3) + (tg << 1);
            float b0v = bias[c], b1v = bias[c + 1];
            float a;
            a = lrelu(fmaf(oacc[nf][0], inv0, b0v)); v0[2*nf]   = a; s0 += a;
            a = lrelu(fmaf(oacc[nf][1], inv0, b1v)); v0[2*nf+1] = a; s0 += a;
            a = lrelu(fmaf(oacc[nf][2], inv1, b0v)); v1[2*nf]   = a; s1 += a;
            a = lrelu(fmaf(oacc[nf][3], inv1, b1v)); v1[2*nf+1] = a; s1 += a;
        }
        s0 += __shfl_xor_sync(0xffffffffu, s0, 1);
        s0 += __shfl_xor_sync(0xffffffffu, s0, 2);
        s1 += __shfl_xor_sync(0xffffffffu, s1, 1);
        s1 += __shfl_xor_sync(0xffffffffu, s1, 2);
        float mu0 = s0 * (1.f / 64.f), mu1 = s1 * (1.f / 64.f);
        float q0 = 0.f, q1 = 0.f;
        #pragma unroll
        for (int i = 0; i < 16; ++i) {
            float u0 = v0[i] - mu0; q0 += u0 * u0;
            float u1 = v1[i] - mu1; q1 += u1 * u1;
        }
        q0 += __shfl_xor_sync(0xffffffffu, q0, 1);
        q0 += __shfl_xor_sync(0xffffffffu, q0, 2);
        q1 += __shfl_xor_sync(0xffffffffu, q1, 1);
        q1 += __shfl_xor_sync(0xffffffffu, q1, 2);
        float rstd0 = rsqrtf(q0 * (1.f / 64.f) + 1e-5f);
        float rstd1 = rsqrtf(q1 * (1.f / 64.f) + 1e-5f);
        float* od0 = outp + ((size_t)bh * N_ + grow0) * D_;
        float* od1 = od0 + 8 * D_;
        #pragma unroll
        for (int nf = 0; nf < 8; ++nf) {
            int c = (nf << 3) + (tg << 1);
            float ga0 = gamma[c], ga1 = gamma[c + 1];
            float be0 = beta[c],  be1 = beta[c + 1];
            float2 w0, w1;
            w0.x = (v0[2*nf]   - mu0) * rstd0 * ga0 + be0;
            w0.y = (v0[2*nf+1] - mu0) * rstd0 * ga1 + be1;
            w1.x = (v1[2*nf]   - mu1) * rstd1 * ga0 + be0;
            w1.y = (v1[2*nf+1] - mu1) * rstd1 * ga1 + be1;
            *(float2*)&od0[c] = w0;
            *(float2*)&od1[c] = w1;
        }
    }
}

// ---------------- launch -----------------------------------------------------
extern "C" void kernel_launch(void* const* d_in, const int* in_sizes, int n_in,
                              void* d_out, int out_size) {
    const float* x     = (const float*)d_in[0];
    const int*   graph = (const int*)  d_in[1];
    const float* Wh    = (const float*)d_in[2];
    const float* bh    = (const float*)d_in[3];
    const float* Wo    = (const float*)d_in[4];
    const float* bo    = (const float*)d_in[5];
    const float* gamma = (const float*)d_in[6];
    const float* beta  = (const float*)d_in[7];
    float* out = (float*)d_out;

    cudaFuncSetAttribute((const void*)attn_mma<1, 4>,
                         cudaFuncAttributeMaxDynamicSharedMemorySize, SMEM_ATT(4));
    cudaFuncSetAttribute((const void*)attn_mma<2, 2>,
                         cudaFuncAttributeMaxDynamicSharedMemorySize, SMEM_ATT(2));

    convert_wo_kernel<<<64, 256>>>(Wo);
    build_mask_kernel<<<(N_ * NW_) / 8, 256>>>(graph);
    proj1_kernel<<<dim3(B_ * N_ / 64, H_), 256>>>(x, Wh);
    attn_mma<1, 4><<<dim3(B_ * H_, N_ / 64), 128, SMEM_ATT(4)>>>(bh, nullptr, nullptr, nullptr);
    reduce_h2_kernel<<<(B_ * N_ * 32) / 256, 256>>>();
    attn_mma<2, 2><<<dim3(B_, N_ / 32), 64, SMEM_ATT(2)>>>(bo, gamma, beta, out);
}

// round 16
// speedup vs baseline: 1.4152x; 1.0475x over previous
#include <cuda_runtime.h>
#include <cuda_fp16.h>
#include <cstdint>

// Problem shape (fixed for this registry entry)
#define B_  8
#define N_  2048
#define C_  64
#define H_  4
#define D_  64
#define HD_ 256          // H*D
#define NW_ (N_/32)      // mask words per row = 64
#define LOG2E 1.4426950408889634f

// ---------------- scratch (device globals: no allocation allowed) -----------
__device__ __half  g_hH [B_*H_*N_*D_];    // layer1 features, f16 hi
__device__ __half  g_hL [B_*H_*N_*D_];    // layer1 features, f16 lo (residual)
__device__ __half  g_h2H[B_*N_*D_];       // layer2 features hi
__device__ __half  g_h2L[B_*N_*D_];       // layer2 features lo
__device__ float   g_h2p[B_*H_*N_*D_];    // per-head partial h2 (deterministic)
__device__ __half  g_WoH[D_*HD_];         // Wo f16 hi
__device__ __half  g_WoL[D_*HD_];         // Wo f16 lo
__device__ __half  g_xH [B_*N_*C_];       // x f16 hi
__device__ __half  g_xL [B_*N_*C_];       // x f16 lo
__device__ unsigned g_maskT[NW_*N_];      // transposed bitmask [w][n]

__device__ __forceinline__ float ex2(float x) {
    float y;
    asm("ex2.approx.f32 %0, %1;" : "=f"(y) : "f"(x));
    return y;
}
__device__ __forceinline__ uint32_t smem_u32(const void* p) {
    uint32_t a;
    asm("{ .reg .u64 t; cvta.to.shared.u64 t, %1; cvt.u32.u64 %0, t; }" : "=r"(a) : "l"(p));
    return a;
}
__device__ __forceinline__ void cp16(uint32_t saddr, const void* g) {
    asm volatile("cp.async.ca.shared.global [%0], [%1], 16;"
                 :: "r"(saddr), "l"(__cvta_generic_to_global(g)));
}
__device__ __forceinline__ void ldsm4(uint32_t r[4], uint32_t addr) {
    asm volatile("ldmatrix.sync.aligned.m8n8.x4.shared.b16 {%0,%1,%2,%3}, [%4];"
                 : "=r"(r[0]), "=r"(r[1]), "=r"(r[2]), "=r"(r[3]) : "r"(addr));
}
__device__ __forceinline__ void ldsm4t(uint32_t r[4], uint32_t addr) {
    asm volatile("ldmatrix.sync.aligned.m8n8.x4.trans.shared.b16 {%0,%1,%2,%3}, [%4];"
                 : "=r"(r[0]), "=r"(r[1]), "=r"(r[2]), "=r"(r[3]) : "r"(addr));
}
__device__ __forceinline__ void mma16816(float d[4], const uint32_t a[4], const uint32_t b[2]) {
    asm volatile("mma.sync.aligned.m16n8k16.row.col.f32.f16.f16.f32 "
                 "{%0,%1,%2,%3}, {%4,%5,%6,%7}, {%8,%9}, {%0,%1,%2,%3};"
                 : "+f"(d[0]), "+f"(d[1]), "+f"(d[2]), "+f"(d[3])
                 : "r"(a[0]), "r"(a[1]), "r"(a[2]), "r"(a[3]), "r"(b[0]), "r"(b[1]));
}
__device__ __forceinline__ float lrelu(float a) { return a > 0.f ? a : 0.2f * a; }

__device__ __forceinline__ void split_store(__half* dH, __half* dL, size_t idx,
                                            float v0, float v1) {
    __half h0 = __float2half_rn(v0), h1 = __float2half_rn(v1);
    __half l0 = __float2half_rn(v0 - __half2float(h0));
    __half l1 = __float2half_rn(v1 - __half2float(h1));
    *(__half2*)&dH[idx] = __halves2half2(h0, h1);
    *(__half2*)&dL[idx] = __halves2half2(l0, l1);
}

// ---------------- one-time conversions ---------------------------------------
__global__ void convert_wo_kernel(const float* __restrict__ Wo) {
    int i = blockIdx.x * 256 + threadIdx.x;
    float w = Wo[i];
    __half hh = __float2half_rn(w);
    g_WoH[i] = hh;
    g_WoL[i] = __float2half_rn(w - __half2float(hh));
}
__global__ void convert_x_kernel(const float* __restrict__ x) {
    int i = (blockIdx.x * 256 + threadIdx.x) * 2;
    float2 v = *(const float2*)&x[i];
    split_store(g_xH, g_xL, i, v.x, v.y);
}

// ---------------- mask build ------------------------------------------------
__global__ void build_mask_kernel(const int* __restrict__ graph) {
    int gwarp = (blockIdx.x * blockDim.x + threadIdx.x) >> 5;
    int lane  = threadIdx.x & 31;
    if (gwarp >= N_ * NW_) return;
    int n = gwarp >> 6;
    int w = gwarp & (NW_ - 1);
    int m = w * 32 + lane;
    bool bit = (graph[(size_t)n * N_ + m] != 0) || (m == n);
    unsigned word = __ballot_sync(0xffffffffu, bit);
    if (lane == 0) g_maskT[w * N_ + n] = word;
}

// ---------------- proj1 via HMMA: h = x @ Wh[h]^T (3-term f16 split) --------
#define P1SQ 72
__global__ void __launch_bounds__(128, 4)
proj1_mma(const float* __restrict__ Wh) {
    __shared__ __half sm[4 * 64 * P1SQ];     // XH, XL, WH, WL : 36864 B
    const int t    = threadIdx.x;
    const int wid  = t >> 5;
    const int lane = t & 31;
    const int g    = lane >> 2;
    const int tg   = lane & 3;
    const int wr0  = wid << 4;
    const int row0 = blockIdx.x * 64;        // flattened b*N + n
    const int h    = blockIdx.y;
    __half* XH = sm;
    __half* XL = sm + 64 * P1SQ;
    __half* WHs = sm + 2 * 64 * P1SQ;
    __half* WLs = sm + 3 * 64 * P1SQ;

    // stage x rows (hi/lo from pre-split globals)
    {
        const uint4* sH = (const uint4*)(g_xH + (size_t)row0 * C_);
        const uint4* sL = (const uint4*)(g_xL + (size_t)row0 * C_);
        #pragma unroll
        for (int i = 0; i < 4; ++i) {
            int idx = t + (i << 7);
            int r = idx >> 3, c8 = (idx & 7) << 3;
            *(uint4*)&XH[r * P1SQ + c8] = sH[idx];
            *(uint4*)&XL[r * P1SQ + c8] = sL[idx];
        }
        // stage Wh head slice, splitting f32 -> f16 hi/lo on the fly
        const float2* wsrc = (const float2*)(Wh + (size_t)h * D_ * C_);
        #pragma unroll
        for (int i = 0; i < 16; ++i) {
            int idx = t + (i << 7);            // 0..2047 float2
            int r = idx >> 5, c2 = (idx & 31) << 1;
            float2 v = wsrc[idx];
            __half h0 = __float2half_rn(v.x), h1 = __float2half_rn(v.y);
            *(__half2*)&WHs[r * P1SQ + c2] = __halves2half2(h0, h1);
            *(__half2*)&WLs[r * P1SQ + c2] = __halves2half2(
                __float2half_rn(v.x - __half2float(h0)),
                __float2half_rn(v.y - __half2float(h1)));
        }
    }
    __syncthreads();

    const uint32_t sb = smem_u32(sm);
    const int arow  = wr0 + (lane & 15);
    const int acolb = (lane >> 4) << 3;
    const int brow  = ((lane >> 4) << 3) + (lane & 7);
    const int bcol  = ((lane >> 3) & 1) << 3;
    const uint32_t xhb = sb;
    const uint32_t xlb = sb + (uint32_t)(64 * P1SQ) * 2;
    const uint32_t whb = sb + (uint32_t)(2 * 64 * P1SQ) * 2;
    const uint32_t wlb = sb + (uint32_t)(3 * 64 * P1SQ) * 2;

    float acc[8][4];
    #pragma unroll
    for (int i = 0; i < 8; ++i)
        #pragma unroll
        for (int j = 0; j < 4; ++j) acc[i][j] = 0.f;

    #pragma unroll
    for (int kf = 0; kf < 4; ++kf) {
        uint32_t ah[4], al[4];
        ldsm4(ah, xhb + ((uint32_t)(arow * P1SQ + (kf << 4) + acolb) << 1));
        ldsm4(al, xlb + ((uint32_t)(arow * P1SQ + (kf << 4) + acolb) << 1));
        #pragma unroll
        for (int hs = 0; hs < 2; ++hs) {
            uint32_t bfr[4][2];
            #pragma unroll
            for (int j = 0; j < 2; ++j) {
                uint32_t r4[4];
                int jj = hs * 2 + j;
                ldsm4(r4, whb + ((uint32_t)(((jj << 4) + brow) * P1SQ
                                            + (kf << 4) + bcol) << 1));
                bfr[2*j][0] = r4[0]; bfr[2*j][1] = r4[1];
                bfr[2*j+1][0] = r4[2]; bfr[2*j+1][1] = r4[3];
            }
            #pragma unroll
            for (int nf = 0; nf < 4; ++nf) mma16816(acc[hs*4+nf], ah, bfr[nf]);
            #pragma unroll
            for (int nf = 0; nf < 4; ++nf) mma16816(acc[hs*4+nf], al, bfr[nf]);
            #pragma unroll
            for (int j = 0; j < 2; ++j) {
                uint32_t r4[4];
                int jj = hs * 2 + j;
                ldsm4(r4, wlb + ((uint32_t)(((jj << 4) + brow) * P1SQ
                                            + (kf << 4) + bcol) << 1));
                bfr[2*j][0] = r4[0]; bfr[2*j][1] = r4[1];
                bfr[2*j+1][0] = r4[2]; bfr[2*j+1][1] = r4[3];
            }
            #pragma unroll
            for (int nf = 0; nf < 4; ++nf) mma16816(acc[hs*4+nf], ah, bfr[nf]);
        }
    }

    const int b     = row0 >> 11;
    const int nbase = row0 & (N_ - 1);
    size_t base0 = (((size_t)(b * H_ + h) * N_) + nbase + wr0 + g) * D_;
    size_t base1 = base0 + 8 * D_;
    #pragma unroll
    for (int nf = 0; nf < 8; ++nf) {
        int d = (nf << 3) + (tg << 1);
        split_store(g_hH, g_hL, base0 + d, acc[nf][0], acc[nf][1]);
        split_store(g_hH, g_hL, base1 + d, acc[nf][2], acc[nf][3]);
    }
}

// ---------------- reduce_h2: sum 4 head partials, split to f16 hi/lo --------
__global__ void reduce_h2_kernel() {
    int idx = blockIdx.x * 256 + threadIdx.x;    // float2 units
    int d2 = idx & 31;
    int n  = (idx >> 5) & (N_ - 1);
    int b  = idx >> 16;
    float2 s = make_float2(0.f, 0.f);
    #pragma unroll
    for (int h = 0; h < H_; ++h) {
        float2 v = *(const float2*)&g_h2p[(((size_t)(b * H_ + h) * N_) + n) * D_ + d2 * 2];
        s.x += v.x; s.y += v.y;
    }
    split_store(g_h2H, g_h2L, ((size_t)(b * N_ + n)) * D_ + d2 * 2, s.x, s.y);
}

// ================= HMMA flash attention, NW warps / NW*16 rows ==============
#define SQ 72                          // smem row stride in halves
#define NT 32                          // KV tiles
#define KBUF_HALVES 4608               // KH[64][72]
#define SMEM_ATT(NWv) ((2 * ((NWv)*16*SQ) + 3 * KBUF_HALVES) * 2)

template <int LAYER, int NW>
__global__ void __launch_bounds__(NW * 32, 4)
attn_mma(const float* __restrict__ bias,
         const float* __restrict__ gamma,
         const float* __restrict__ beta,
         float* __restrict__ outp) {
    constexpr int ROWS   = NW * 16;
    constexpr int NTHR   = NW * 32;
    constexpr int SM_QH  = 0;
    constexpr int SM_QL  = ROWS * SQ;
    constexpr int SM_K   = 2 * ROWS * SQ;
    constexpr int KIT    = 512 / NTHR;

    extern __shared__ __half smh[];
    const int t    = threadIdx.x;
    const int wid  = t >> 5;
    const int lane = t & 31;
    const int g    = lane >> 2;
    const int tg   = lane & 3;
    const int wr0  = wid << 4;
    const int bh   = blockIdx.x;
    const int row0 = blockIdx.y * ROWS;
    const __half* hH = (LAYER == 1 ? g_hH : g_h2H) + (size_t)bh * (N_ * D_);
    const __half* hL = (LAYER == 1 ? g_hL : g_h2L) + (size_t)bh * (N_ * D_);
    const uint32_t sbase = smem_u32(smh);

    // ---- stage Q hi + lo (ROWS rows) ----
    {
        const uint4* sH = (const uint4*)(hH + (size_t)row0 * D_);
        const uint4* sL = (const uint4*)(hL + (size_t)row0 * D_);
        #pragma unroll
        for (int i = 0; i < 4; ++i) {
            int idx = t + i * NTHR;
            int r = idx >> 3, c8 = (idx & 7) << 3;
            *(uint4*)&smh[SM_QH + r * SQ + c8] = sH[idx];
            *(uint4*)&smh[SM_QL + r * SQ + c8] = sL[idx];
        }
    }
    // ---- prefetch K tiles 0,1 (hi only) into ring buffers 0,1 ----
    #pragma unroll
    for (int pt = 0; pt < 2; ++pt) {
        const uint4* sH = (const uint4*)(hH + (size_t)pt * (64 * D_));
        uint32_t kb = sbase + (uint32_t)(SM_K + pt * KBUF_HALVES) * 2;
        #pragma unroll
        for (int i = 0; i < KIT; ++i) {
            int idx = t + i * NTHR;
            int r = idx >> 3, c8 = (idx & 7) << 3;
            cp16(kb + (((uint32_t)(r * SQ + c8)) << 1), sH + idx);
        }
        asm volatile("cp.async.commit_group;" ::: "memory");
    }
    __syncthreads();

    // ---- preload Q-hi A-frags; Q-lo transient ----
    const int arow  = wr0 + (lane & 15);
    const int acolb = (lane >> 4) << 3;
    uint32_t qh[4][4];
    #pragma unroll
    for (int kf = 0; kf < 4; ++kf)
        ldsm4(qh[kf], sbase + ((uint32_t)(SM_QH + arow * SQ + (kf << 4) + acolb) << 1));

    float oacc[8][4];
    #pragma unroll
    for (int i = 0; i < 8; ++i)
        #pragma unroll
        for (int j = 0; j < 4; ++j) oacc[i][j] = 0.f;
    float rs0 = 0.f, rs1 = 0.f, mr0 = -1e30f, mr1 = -1e30f;
    const int grow0 = row0 + wr0 + g;

    int buf = 0;
    #pragma unroll 1
    for (int tile = 0; tile < NT; ++tile) {
        asm volatile("cp.async.wait_group 1;" ::: "memory");
        __syncthreads();
        // ---- prefetch tile+2 into ring slot ----
        {
            int pt = tile + 2;
            if (pt < NT) {
                int pb = buf + 2; if (pb >= 3) pb -= 3;
                const uint4* sH = (const uint4*)(hH + (size_t)pt * (64 * D_));
                uint32_t kb = sbase + (uint32_t)(SM_K + pb * KBUF_HALVES) * 2;
                #pragma unroll
                for (int i = 0; i < KIT; ++i) {
                    int idx = t + i * NTHR;
                    int r = idx >> 3, c8 = (idx & 7) << 3;
                    cp16(kb + (((uint32_t)(r * SQ + c8)) << 1), sH + idx);
                }
            }
            asm volatile("cp.async.commit_group;" ::: "memory");   // empty group ok
        }
        unsigned mw0[2], mw1[2];
        #pragma unroll
        for (int w = 0; w < 2; ++w) {
            mw0[w] = g_maskT[(size_t)((tile << 1) + w) * N_ + grow0];
            mw1[w] = g_maskT[(size_t)((tile << 1) + w) * N_ + grow0 + 8];
        }

        const uint32_t kbH = sbase + (uint32_t)(SM_K + buf * KBUF_HALVES) * 2;

        // ---- GEMM-S: sacc = Qh*Kh + Ql*Kh (Ql transient; bfr chunked) ----
        float sacc[8][4];
        #pragma unroll
        for (int i = 0; i < 8; ++i)
            #pragma unroll
            for (int j = 0; j < 4; ++j) sacc[i][j] = 0.f;
        {
            const int brow = ((lane >> 4) << 3) + (lane & 7);
            const int bcol = ((lane >> 3) & 1) << 3;
            #pragma unroll
            for (int kf = 0; kf < 4; ++kf) {
                uint32_t qlt[4];
                ldsm4(qlt, sbase + ((uint32_t)(SM_QL + arow * SQ + (kf << 4) + acolb) << 1));
                #pragma unroll
                for (int hs = 0; hs < 2; ++hs) {
                    uint32_t bfr[4][2];
                    #pragma unroll
                    for (int j = 0; j < 2; ++j) {
                        uint32_t r4[4];
                        int jj = hs * 2 + j;
                        ldsm4(r4, kbH + ((uint32_t)(((jj << 4) + brow) * SQ
                                                    + (kf << 4) + bcol) << 1));
                        bfr[2*j][0] = r4[0]; bfr[2*j][1] = r4[1];
                        bfr[2*j+1][0] = r4[2]; bfr[2*j+1][1] = r4[3];
                    }
                    #pragma unroll
                    for (int nf = 0; nf < 4; ++nf) mma16816(sacc[hs*4+nf], qh[kf], bfr[nf]);
                    #pragma unroll
                    for (int nf = 0; nf < 4; ++nf) mma16816(sacc[hs*4+nf], qlt, bfr[nf]);
                }
            }
        }

        // ---- softmax: unmasked tile max (upper bound, f16-safe) ----
        float m0 = -1e30f, m1 = -1e30f;
        #pragma unroll
        for (int nf = 0; nf < 8; ++nf) {
            m0 = fmaxf(m0, fmaxf(sacc[nf][0], sacc[nf][1]));
            m1 = fmaxf(m1, fmaxf(sacc[nf][2], sacc[nf][3]));
        }
        m0 = fmaxf(m0, __shfl_xor_sync(0xffffffffu, m0, 1));
        m0 = fmaxf(m0, __shfl_xor_sync(0xffffffffu, m0, 2));
        m1 = fmaxf(m1, __shfl_xor_sync(0xffffffffu, m1, 1));
        m1 = fmaxf(m1, __shfl_xor_sync(0xffffffffu, m1, 2));
        float mn0 = fmaxf(mr0, m0), mn1 = fmaxf(mr1, m1);
        float al0 = ex2((mr0 - mn0) * LOG2E), al1 = ex2((mr1 - mn1) * LOG2E);
        mr0 = mn0; mr1 = mn1;
        if (__any_sync(0xffffffffu, (al0 != 1.f) || (al1 != 1.f))) {
            rs0 *= al0; rs1 *= al1;
            #pragma unroll
            for (int nf = 0; nf < 8; ++nf) {
                oacc[nf][0] *= al0; oacc[nf][1] *= al0;
                oacc[nf][2] *= al1; oacc[nf][3] *= al1;
            }
        }
        const float mL0 = mn0 * LOG2E, mL1 = mn1 * LOG2E;
        uint32_t pa[4][4];
        #pragma unroll
        for (int k2 = 0; k2 < 4; ++k2) {
            int nfA = k2 << 1, nfB = nfA + 1;
            unsigned wA0 = mw0[nfA >> 2], wA1 = mw1[nfA >> 2];
            unsigned wB0 = mw0[nfB >> 2], wB1 = mw1[nfB >> 2];
            int bbA = ((nfA & 3) << 3) + (tg << 1);
            int bbB = ((nfB & 3) << 3) + (tg << 1);
            float p00 = ((wA0 >> bbA) & 1u)     ? ex2(fmaf(sacc[nfA][0], LOG2E, -mL0)) : 0.f;
            float p01 = ((wA0 >> (bbA+1)) & 1u) ? ex2(fmaf(sacc[nfA][1], LOG2E, -mL0)) : 0.f;
            float p02 = ((wA1 >> bbA) & 1u)     ? ex2(fmaf(sacc[nfA][2], LOG2E, -mL1)) : 0.f;
            float p03 = ((wA1 >> (bbA+1)) & 1u) ? ex2(fmaf(sacc[nfA][3], LOG2E, -mL1)) : 0.f;
            float p10 = ((wB0 >> bbB) & 1u)     ? ex2(fmaf(sacc[nfB][0], LOG2E, -mL0)) : 0.f;
            float p11 = ((wB0 >> (bbB+1)) & 1u) ? ex2(fmaf(sacc[nfB][1], LOG2E, -mL0)) : 0.f;
            float p12 = ((wB1 >> bbB) & 1u)     ? ex2(fmaf(sacc[nfB][2], LOG2E, -mL1)) : 0.f;
            float p13 = ((wB1 >> (bbB+1)) & 1u) ? ex2(fmaf(sacc[nfB][3], LOG2E, -mL1)) : 0.f;
            __half2 h0 = __floats2half2_rn(p00, p01);
            __half2 h1 = __floats2half2_rn(p02, p03);
            __half2 h2 = __floats2half2_rn(p10, p11);
            __half2 h3 = __floats2half2_rn(p12, p13);
            pa[k2][0] = *(uint32_t*)&h0; pa[k2][1] = *(uint32_t*)&h1;
            pa[k2][2] = *(uint32_t*)&h2; pa[k2][3] = *(uint32_t*)&h3;
            float2 f0 = __half22float2(h0), f2 = __half22float2(h2);
            float2 f1 = __half22float2(h1), f3 = __half22float2(h3);
            rs0 += (f0.x + f0.y) + (f2.x + f2.y);
            rs1 += (f1.x + f1.y) + (f3.x + f3.y);
        }

        // ---- GEMM-A: O += P * Vh ----
        {
            const int brow  = (((lane >> 3) & 1) << 3) + (lane & 7);
            const int bcolb = (lane >> 4) << 3;
            #pragma unroll
            for (int kf = 0; kf < 4; ++kf) {
                #pragma unroll
                for (int hs = 0; hs < 2; ++hs) {
                    uint32_t bv[4][2];
                    #pragma unroll
                    for (int j = 0; j < 2; ++j) {
                        uint32_t r4[4];
                        int jj = hs * 2 + j;
                        ldsm4t(r4, kbH + ((uint32_t)(((kf << 4) + brow) * SQ
                                                     + (jj << 4) + bcolb) << 1));
                        bv[2*j][0] = r4[0]; bv[2*j][1] = r4[1];
                        bv[2*j+1][0] = r4[2]; bv[2*j+1][1] = r4[3];
                    }
                    #pragma unroll
                    for (int nf = 0; nf < 4; ++nf) mma16816(oacc[hs*4+nf], pa[kf], bv[nf]);
                }
            }
        }
        if (++buf == 3) buf = 0;
    }

    // ---- finalize: rowsum quad-reduce ----
    rs0 += __shfl_xor_sync(0xffffffffu, rs0, 1);
    rs0 += __shfl_xor_sync(0xffffffffu, rs0, 2);
    rs1 += __shfl_xor_sync(0xffffffffu, rs1, 1);
    rs1 += __shfl_xor_sync(0xffffffffu, rs1, 2);
    float inv0 = 1.f / rs0, inv1 = 1.f / rs1;

    if (LAYER == 1) {
        // ---- fused proj2 slice: h2_partial = lrelu(z_slice) @ Wo_slice^T ----
        const int h = bh & (H_ - 1);
        #pragma unroll
        for (int nf = 0; nf < 8; ++nf) {
            int c = (nf << 3) + (tg << 1);
            float b0v = bias[h * D_ + c], b1v = bias[h * D_ + c + 1];
            oacc[nf][0] = lrelu(fmaf(oacc[nf][0], inv0, b0v));
            oacc[nf][1] = lrelu(fmaf(oacc[nf][1], inv0, b1v));
            oacc[nf][2] = lrelu(fmaf(oacc[nf][2], inv1, b0v));
            oacc[nf][3] = lrelu(fmaf(oacc[nf][3], inv1, b1v));
        }
        uint32_t zh[4][4], zl[4][4];
        #pragma unroll
        for (int kf = 0; kf < 4; ++kf) {
            int nfA = kf << 1, nfB = nfA + 1;
            __half2 hA0 = __floats2half2_rn(oacc[nfA][0], oacc[nfA][1]);
            __half2 hA1 = __floats2half2_rn(oacc[nfA][2], oacc[nfA][3]);
            __half2 hB0 = __floats2half2_rn(oacc[nfB][0], oacc[nfB][1]);
            __half2 hB1 = __floats2half2_rn(oacc[nfB][2], oacc[nfB][3]);
            float2 fA0 = __half22float2(hA0), fA1 = __half22float2(hA1);
            float2 fB0 = __half22float2(hB0), fB1 = __half22float2(hB1);
            __half2 lA0 = __floats2half2_rn(oacc[nfA][0] - fA0.x, oacc[nfA][1] - fA0.y);
            __half2 lA1 = __floats2half2_rn(oacc[nfA][2] - fA1.x, oacc[nfA][3] - fA1.y);
            __half2 lB0 = __floats2half2_rn(oacc[nfB][0] - fB0.x, oacc[nfB][1] - fB0.y);
            __half2 lB1 = __floats2half2_rn(oacc[nfB][2] - fB1.x, oacc[nfB][3] - fB1.y);
            zh[kf][0] = *(uint32_t*)&hA0; zh[kf][1] = *(uint32_t*)&hA1;
            zh[kf][2] = *(uint32_t*)&hB0; zh[kf][3] = *(uint32_t*)&hB1;
            zl[kf][0] = *(uint32_t*)&lA0; zl[kf][1] = *(uint32_t*)&lA1;
            zl[kf][2] = *(uint32_t*)&lB0; zl[kf][3] = *(uint32_t*)&lB1;
        }
        __syncthreads();
        #pragma unroll
        for (int i = 0; i < 4; ++i) {
            int idx = t + i * NTHR;
            int r = idx >> 3, c8 = (idx & 7) << 3;
            *(uint4*)&smh[SM_K + r * SQ + c8] =
                *(const uint4*)(g_WoH + (size_t)r * HD_ + h * D_ + c8);
            *(uint4*)&smh[SM_K + KBUF_HALVES + r * SQ + c8] =
                *(const uint4*)(g_WoL + (size_t)r * HD_ + h * D_ + c8);
        }
        __syncthreads();
        float o2[8][4];
        #pragma unroll
        for (int i = 0; i < 8; ++i)
            #pragma unroll
            for (int j = 0; j < 4; ++j) o2[i][j] = 0.f;
        {
            const int brow = ((lane >> 4) << 3) + (lane & 7);
            const int bcol = ((lane >> 3) & 1) << 3;
            const uint32_t wbH = sbase + (uint32_t)SM_K * 2;
            const uint32_t wbL = wbH + ((uint32_t)KBUF_HALVES << 1);
            #pragma unroll
            for (int kf = 0; kf < 4; ++kf) {
                #pragma unroll
                for (int hs = 0; hs < 2; ++hs) {
                    uint32_t bfr[4][2];
                    #pragma unroll
                    for (int j = 0; j < 2; ++j) {
                        uint32_t r4[4];
                        int jj = hs * 2 + j;
                        ldsm4(r4, wbH + ((uint32_t)(((jj << 4) + brow) * SQ
                                                    + (kf << 4) + bcol) << 1));
                        bfr[2*j][0] = r4[0]; bfr[2*j][1] = r4[1];
                        bfr[2*j+1][0] = r4[2]; bfr[2*j+1][1] = r4[3];
                    }
                    #pragma unroll
                    for (int nf = 0; nf < 4; ++nf) mma16816(o2[hs*4+nf], zh[kf], bfr[nf]);
                    #pragma unroll
                    for (int nf = 0; nf < 4; ++nf) mma16816(o2[hs*4+nf], zl[kf], bfr[nf]);
                    #pragma unroll
                    for (int j = 0; j < 2; ++j) {
                        uint32_t r4[4];
                        int jj = hs * 2 + j;
                        ldsm4(r4, wbL + ((uint32_t)(((jj << 4) + brow) * SQ
                                                    + (kf << 4) + bcol) << 1));
                        bfr[2*j][0] = r4[0]; bfr[2*j][1] = r4[1];
                        bfr[2*j+1][0] = r4[2]; bfr[2*j+1][1] = r4[3];
                    }
                    #pragma unroll
                    for (int nf = 0; nf < 4; ++nf) mma16816(o2[hs*4+nf], zh[kf], bfr[nf]);
                }
            }
        }
        size_t rb = ((size_t)bh * N_ + grow0) * D_;
        #pragma unroll
        for (int nf = 0; nf < 8; ++nf) {
            int d = (nf << 3) + (tg << 1);
            *(float2*)&g_h2p[rb + d]           = make_float2(o2[nf][0], o2[nf][1]);
            *(float2*)&g_h2p[rb + 8 * D_ + d]  = make_float2(o2[nf][2], o2[nf][3]);
        }
    } else {
        float v0[16], v1[16];
        float s0 = 0.f, s1 = 0.f;
        #pragma unroll
        for (int nf = 0; nf < 8; ++nf) {
            int c = (nf << 3) + (tg << 1);
            float b0v = bias[c], b1v = bias[c + 1];
            float a;
            a = lrelu(fmaf(oacc[nf][0], inv0, b0v)); v0[2*nf]   = a; s0 += a;
            a = lrelu(fmaf(oacc[nf][1], inv0, b1v)); v0[2*nf+1] = a; s0 += a;
            a = lrelu(fmaf(oacc[nf][2], inv1, b0v)); v1[2*nf]   = a; s1 += a;
            a = lrelu(fmaf(oacc[nf][3], inv1, b1v)); v1[2*nf+1] = a; s1 += a;
        }
        s0 += __shfl_xor_sync(0xffffffffu, s0, 1);
        s0 += __shfl_xor_sync(0xffffffffu, s0, 2);
        s1 += __shfl_xor_sync(0xffffffffu, s1, 1);
        s1 += __shfl_xor_sync(0xffffffffu, s1, 2);
        float mu0 = s0 * (1.f / 64.f), mu1 = s1 * (1.f / 64.f);
        float q0 = 0.f, q1 = 0.f;
        #pragma unroll
        for (int i = 0; i < 16; ++i) {
            float u0 = v0[i] - mu0; q0 += u0 * u0;
            float u1 = v1[i] - mu1; q1 += u1 * u1;
        }
        q0 += __shfl_xor_sync(0xffffffffu, q0, 1);
        q0 += __shfl_xor_sync(0xffffffffu, q0, 2);
        q1 += __shfl_xor_sync(0xffffffffu, q1, 1);
        q1 += __shfl_xor_sync(0xffffffffu, q1, 2);
        float rstd0 = rsqrtf(q0 * (1.f / 64.f) + 1e-5f);
        float rstd1 = rsqrtf(q1 * (1.f / 64.f) + 1e-5f);
        float* od0 = outp + ((size_t)bh * N_ + grow0) * D_;
        float* od1 = od0 + 8 * D_;
        #pragma unroll
        for (int nf = 0; nf < 8; ++nf) {
            int c = (nf << 3) + (tg << 1);
            float ga0 = gamma[c], ga1 = gamma[c + 1];
            float be0 = beta[c],  be1 = beta[c + 1];
            float2 w0, w1;
            w0.x = (v0[2*nf]   - mu0) * rstd0 * ga0 + be0;
            w0.y = (v0[2*nf+1] - mu0) * rstd0 * ga1 + be1;
            w1.x = (v1[2*nf]   - mu1) * rstd1 * ga0 + be0;
            w1.y = (v1[2*nf+1] - mu1) * rstd1 * ga1 + be1;
            *(float2*)&od0[c] = w0;
            *(float2*)&od1[c] = w1;
        }
    }
}

// ---------------- launch -----------------------------------------------------
extern "C" void kernel_launch(void* const* d_in, const int* in_sizes, int n_in,
                              void* d_out, int out_size) {
    const float* x     = (const float*)d_in[0];
    const int*   graph = (const int*)  d_in[1];
    const float* Wh    = (const float*)d_in[2];
    const float* bh    = (const float*)d_in[3];
    const float* Wo    = (const float*)d_in[4];
    const float* bo    = (const float*)d_in[5];
    const float* gamma = (const float*)d_in[6];
    const float* beta  = (const float*)d_in[7];
    float* out = (float*)d_out;

    cudaFuncSetAttribute((const void*)attn_mma<1, 4>,
                         cudaFuncAttributeMaxDynamicSharedMemorySize, SMEM_ATT(4));
    cudaFuncSetAttribute((const void*)attn_mma<2, 2>,
                         cudaFuncAttributeMaxDynamicSharedMemorySize, SMEM_ATT(2));

    convert_wo_kernel<<<64, 256>>>(Wo);
    convert_x_kernel<<<(B_ * N_ * C_) / 512, 256>>>(x);
    build_mask_kernel<<<(N_ * NW_) / 8, 256>>>(graph);
    proj1_mma<<<dim3(B_ * N_ / 64, H_), 128>>>(Wh);
    attn_mma<1, 4><<<dim3(B_ * H_, N_ / 64), 128, SMEM_ATT(4)>>>(bh, nullptr, nullptr, nullptr);
    reduce_h2_kernel<<<(B_ * N_ * 32) / 256, 256>>>();
    attn_mma<2, 2><<<dim3(B_, N_ / 32), 64, SMEM_ATT(2)>>>(bo, gamma, beta, out);
}